// round 4
// baseline (speedup 1.0000x reference)
#include <cuda_runtime.h>

#define D      128
#define NN     20000
#define NE     600000
#define ESZ    20

// ---------------- scratch (device globals; no allocations allowed) ----------
__device__ float g_h1[NN * D];        // silu(s@Wm1+bm1)
__device__ float g_so[NN * 3 * D];    // scalar_output
__device__ float g_uv[NN * 3 * D];    // Uv
__device__ float g_vvsq[NN * D];      // sum_axis Vv^2
__device__ float g_ip[NN * D];        // sum_axis Uv*Vv
__device__ float g_h2[NN * D];        // silu([s,Vvsq]@Wa1+ba1)

__device__ __forceinline__ float silu_f(float x) {
    return x / (1.0f + __expf(-x));
}

__device__ __forceinline__ void red2(float* p, float a, float b) {
    asm volatile("red.global.add.v2.f32 [%0], {%1,%2};"
                 :: "l"(p), "f"(a), "f"(b) : "memory");
}

// ---------------- kernel 1: init output with residuals -----------------------
__global__ void k_init(const float* __restrict__ ns, const float* __restrict__ nv,
                       float* __restrict__ out) {
    const float4* a = (const float4*)ns;
    const float4* b = (const float4*)nv;
    float4* os = (float4*)out;
    float4* ov = os + (NN * D) / 4;
    const int ts = NN * D / 4;
    const int tv = NN * 3 * D / 4;
    for (int i = blockIdx.x * blockDim.x + threadIdx.x; i < ts; i += gridDim.x * blockDim.x)
        os[i] = a[i];
    for (int i = blockIdx.x * blockDim.x + threadIdx.x; i < tv; i += gridDim.x * blockDim.x)
        ov[i] = b[i];
}

// ---------------- kernel 2: h1 = silu(ns @ Wm1 + bm1) ------------------------
__global__ void k_mlp1(const float* __restrict__ x, const float* __restrict__ W,
                       const float* __restrict__ b) {
    extern __shared__ float sm[];
    float* Ws = sm;                 // 16384
    float* bs = sm + 16384;         // 128
    float* xs = sm + 16512;         // 512
    int tid = threadIdx.x, g = tid >> 7, c = tid & 127;
    for (int i = tid; i < D * D; i += 512) Ws[i] = W[i];
    if (tid < D) bs[tid] = b[tid];
    __syncthreads();
    int stride = gridDim.x * 4;
    int iters = (NN + stride - 1) / stride;
    for (int it = 0; it < iters; ++it) {
        int n = it * stride + blockIdx.x * 4 + g;
        bool act = n < NN;
        if (act) xs[g * D + c] = x[(long)n * D + c];
        __syncthreads();
        if (act) {
            float acc = bs[c];
#pragma unroll 8
            for (int k = 0; k < D; k++) acc += xs[g * D + k] * Ws[k * D + c];
            g_h1[(long)n * D + c] = silu_f(acc);
        }
        __syncthreads();
    }
}

// ---------------- kernel 3: scalar_output = h1 @ Wm2 + bm2 -------------------
__global__ void __launch_bounds__(512, 1)
k_mlp2(const float* __restrict__ W, const float* __restrict__ b) {
    extern __shared__ float sm[];
    float* Ws = sm;                 // 49152
    float* bs = sm + 49152;         // 384
    int tid = threadIdx.x;
    {
        const float4* Wv = (const float4*)W;
        float4* Wsv = (float4*)Ws;
        for (int i = tid; i < 12288; i += 512) Wsv[i] = Wv[i];
        if (tid < 384) bs[tid] = b[tid];
    }
    __syncthreads();
    int warp = tid >> 5, lane = tid & 31;
    int n0 = blockIdx.x * 64 + warp * 4;

    float xr[4][4];
#pragma unroll
    for (int n = 0; n < 4; n++) {
        int node = n0 + n;
#pragma unroll
        for (int j = 0; j < 4; j++)
            xr[j][n] = (node < NN) ? g_h1[(size_t)node * D + j * 32 + lane] : 0.f;
    }
    float4 b0 = *(float4*)(bs + lane * 4);
    float4 b1 = *(float4*)(bs + 128 + lane * 4);
    float4 b2 = *(float4*)(bs + 256 + lane * 4);
    float4 a0[4], a1[4], a2[4];
#pragma unroll
    for (int n = 0; n < 4; n++) { a0[n] = b0; a1[n] = b1; a2[n] = b2; }

#pragma unroll
    for (int j = 0; j < 4; j++) {
#pragma unroll
        for (int kk = 0; kk < 32; kk++) {
            int k = j * 32 + kk;
            float4 w0 = *(float4*)(Ws + k * 384 + lane * 4);
            float4 w1 = *(float4*)(Ws + k * 384 + 128 + lane * 4);
            float4 w2 = *(float4*)(Ws + k * 384 + 256 + lane * 4);
#pragma unroll
            for (int n = 0; n < 4; n++) {
                float xv = __shfl_sync(0xffffffffu, xr[j][n], kk);
                a0[n].x += xv * w0.x; a0[n].y += xv * w0.y; a0[n].z += xv * w0.z; a0[n].w += xv * w0.w;
                a1[n].x += xv * w1.x; a1[n].y += xv * w1.y; a1[n].z += xv * w1.z; a1[n].w += xv * w1.w;
                a2[n].x += xv * w2.x; a2[n].y += xv * w2.y; a2[n].z += xv * w2.z; a2[n].w += xv * w2.w;
            }
        }
    }
#pragma unroll
    for (int n = 0; n < 4; n++) {
        int node = n0 + n;
        if (node < NN) {
            float* o = g_so + (size_t)node * 384 + lane * 4;
            *(float4*)o = a0[n];
            *(float4*)(o + 128) = a1[n];
            *(float4*)(o + 256) = a2[n];
        }
    }
}

// ---------------- kernel 4: fused edge filter + gather + scatter -------------
// Sextet of 6 independent warps per edge: role r (0..2) x half h (0..1).
// Lane owns 2 cols: col = role*128 + half*64 + lane*2.  Wf slice = 20 float2 regs.
// role 0: gate_nodes * nv[src]  -> 3 red2 into out_v
// role 1: gate_edges * ev       -> 3 red2 into out_v
// role 2: messages_scalar       -> 1 red2 into out_s
__global__ void __launch_bounds__(768, 1)
k_edge(const float* __restrict__ es, const float* __restrict__ ev,
       const float* __restrict__ en, const int* __restrict__ ei,
       const float* __restrict__ Wf, const float* __restrict__ bf,
       const float* __restrict__ nv, float* __restrict__ out) {
    int gwarp = (blockIdx.x * blockDim.x + threadIdx.x) >> 5;
    int lane = threadIdx.x & 31;
    int sext = gwarp / 6, sub = gwarp % 6;
    int role = sub >> 1, half = sub & 1;
    int nsext = (gridDim.x * 768 / 32) / 6;
    int colb = role * 128 + half * 64 + lane * 2;   // filter column base
    int ch   = half * 64 + lane * 2;                // channel within 128-block

    float2 Wreg[ESZ];
#pragma unroll
    for (int k = 0; k < ESZ; k++) Wreg[k] = *(const float2*)(Wf + k * 384 + colb);
    float2 bfr = *(const float2*)(bf + colb);

    float* out_s = out;
    float* out_v = out + (size_t)NN * D;

    int e = sext;
    if (e >= NE) return;
    float esv = (lane < ESZ) ? __ldg(es + (size_t)e * ESZ + lane) : 0.f;
    int2 sd = __ldg((const int2*)(ei) + e);
    float r = __ldg(en + e);

    while (true) {
        int e2 = e + nsext;
        float esv2 = 0.f; int2 sd2 = {0, 0}; float r2 = 0.f;
        if (e2 < NE) {
            esv2 = (lane < ESZ) ? __ldg(es + (size_t)e2 * ESZ + lane) : 0.f;
            sd2 = __ldg((const int2*)(ei) + e2);
            r2 = __ldg(en + e2);
        }
        int src = sd.x, dst = sd.y;
        float fc = (r < 5.0f) ? 0.5f * (cospif(r * 0.2f) + 1.0f) : 0.0f;
        float fx = bfr.x, fy = bfr.y;
#pragma unroll
        for (int k = 0; k < ESZ; k++) {
            float ek = __shfl_sync(0xffffffffu, esv, k);
            fx += ek * Wreg[k].x;
            fy += ek * Wreg[k].y;
        }
        float2 so2 = __ldg((const float2*)(g_so + (size_t)src * 384 + colb));
        float mx = fx * fc * so2.x;
        float my = fy * fc * so2.y;

        if (role == 2) {
            red2(out_s + (size_t)dst * D + ch, mx, my);
        } else if (role == 1) {
            float ev0 = __ldg(ev + 3 * (size_t)e);
            float ev1 = __ldg(ev + 3 * (size_t)e + 1);
            float ev2 = __ldg(ev + 3 * (size_t)e + 2);
            float* ovb = out_v + (size_t)dst * 384 + ch;
            red2(ovb,       mx * ev0, my * ev0);
            red2(ovb + 128, mx * ev1, my * ev1);
            red2(ovb + 256, mx * ev2, my * ev2);
        } else {
            const float* nvb = nv + (size_t)src * 384 + ch;
            float2 n0 = __ldg((const float2*)(nvb));
            float2 n1 = __ldg((const float2*)(nvb + 128));
            float2 n2 = __ldg((const float2*)(nvb + 256));
            float* ovb = out_v + (size_t)dst * 384 + ch;
            red2(ovb,       mx * n0.x, my * n0.y);
            red2(ovb + 128, mx * n1.x, my * n1.y);
            red2(ovb + 256, mx * n2.x, my * n2.y);
        }
        if (e2 >= NE) break;
        e = e2; esv = esv2; sd = sd2; r = r2;
    }
}

// ---------------- kernel 5: Uv, |Vv|^2, <Uv,Vv> ------------------------------
__global__ void k_uv(const float* __restrict__ WU, const float* __restrict__ WV,
                     const float* __restrict__ out) {
    extern __shared__ float sm[];
    float* WUs = sm;
    float* WVs = sm + 16384;
    float* vs = sm + 32768;
    const float* v_in = out + (long)NN * D;
    int tid = threadIdx.x, g = tid >> 7, c = tid & 127;
    for (int i = tid; i < 16384; i += 512) {
        WUs[i] = WU[i];
        WVs[i] = WV[i];
    }
    __syncthreads();
    int stride = gridDim.x * 4;
    int iters = (NN + stride - 1) / stride;
    for (int it = 0; it < iters; ++it) {
        int n = it * stride + blockIdx.x * 4 + g;
        bool act = n < NN;
        if (act) {
            long b = (long)n * 384;
            vs[g * 384 + c]       = v_in[b + c];
            vs[g * 384 + c + 128] = v_in[b + c + 128];
            vs[g * 384 + c + 256] = v_in[b + c + 256];
        }
        __syncthreads();
        if (act) {
            float u0 = 0, u1 = 0, u2 = 0, w0 = 0, w1 = 0, w2 = 0;
#pragma unroll 4
            for (int k = 0; k < D; k++) {
                float wu = WUs[k * D + c], wv = WVs[k * D + c];
                float v0 = vs[g * 384 + k];
                float v1 = vs[g * 384 + 128 + k];
                float v2 = vs[g * 384 + 256 + k];
                u0 += v0 * wu; u1 += v1 * wu; u2 += v2 * wu;
                w0 += v0 * wv; w1 += v1 * wv; w2 += v2 * wv;
            }
            long b = (long)n * 384;
            g_uv[b + c] = u0;
            g_uv[b + c + 128] = u1;
            g_uv[b + c + 256] = u2;
            g_vvsq[(long)n * D + c] = w0 * w0 + w1 * w1 + w2 * w2;
            g_ip[(long)n * D + c]   = u0 * w0 + u1 * w1 + u2 * w2;
        }
        __syncthreads();
    }
}

// ---------------- kernel 6: h2 = silu([s, Vvsq] @ Wa1 + ba1) -----------------
__global__ void __launch_bounds__(512, 1)
k_a1(const float* __restrict__ W, const float* __restrict__ b,
     const float* __restrict__ out) {
    extern __shared__ float sm[];
    float* Ws = sm;                 // 32768
    float* bs = sm + 32768;         // 128
    int tid = threadIdx.x;
    {
        const float4* Wv = (const float4*)W;
        float4* Wsv = (float4*)Ws;
        for (int i = tid; i < 8192; i += 512) Wsv[i] = Wv[i];
        if (tid < 128) bs[tid] = b[tid];
    }
    __syncthreads();
    int warp = tid >> 5, lane = tid & 31;
    int n0 = blockIdx.x * 64 + warp * 4;

    float xr[8][4];
#pragma unroll
    for (int n = 0; n < 4; n++) {
        int node = n0 + n;
        if (node < NN) {
#pragma unroll
            for (int j = 0; j < 4; j++)
                xr[j][n] = out[(size_t)node * D + j * 32 + lane];
#pragma unroll
            for (int j = 0; j < 4; j++)
                xr[4 + j][n] = g_vvsq[(size_t)node * D + j * 32 + lane];
        } else {
#pragma unroll
            for (int j = 0; j < 8; j++) xr[j][n] = 0.f;
        }
    }
    float4 bv = *(float4*)(bs + lane * 4);
    float4 acc[4];
#pragma unroll
    for (int n = 0; n < 4; n++) acc[n] = bv;

#pragma unroll
    for (int j = 0; j < 8; j++) {
#pragma unroll
        for (int kk = 0; kk < 32; kk++) {
            int k = j * 32 + kk;
            float4 w = *(float4*)(Ws + k * D + lane * 4);
#pragma unroll
            for (int n = 0; n < 4; n++) {
                float xv = __shfl_sync(0xffffffffu, xr[j][n], kk);
                acc[n].x += xv * w.x; acc[n].y += xv * w.y;
                acc[n].z += xv * w.z; acc[n].w += xv * w.w;
            }
        }
    }
#pragma unroll
    for (int n = 0; n < 4; n++) {
        int node = n0 + n;
        if (node < NN) {
            float4 o;
            o.x = silu_f(acc[n].x); o.y = silu_f(acc[n].y);
            o.z = silu_f(acc[n].z); o.w = silu_f(acc[n].w);
            *(float4*)(g_h2 + (size_t)node * D + lane * 4) = o;
        }
    }
}

// ---------------- kernel 7: a = h2 @ Wa2 + ba2, final in-place update --------
__global__ void __launch_bounds__(512, 1)
k_a2(const float* __restrict__ W, const float* __restrict__ b,
     float* __restrict__ out) {
    extern __shared__ float sm[];
    float* Ws = sm;                 // 49152
    float* bs = sm + 49152;         // 384
    int tid = threadIdx.x;
    {
        const float4* Wv = (const float4*)W;
        float4* Wsv = (float4*)Ws;
        for (int i = tid; i < 12288; i += 512) Wsv[i] = Wv[i];
        if (tid < 384) bs[tid] = b[tid];
    }
    __syncthreads();
    int warp = tid >> 5, lane = tid & 31;
    int n0 = blockIdx.x * 64 + warp * 4;
    float* out_s = out;
    float* out_v = out + (size_t)NN * D;

    float xr[4][4];
#pragma unroll
    for (int n = 0; n < 4; n++) {
        int node = n0 + n;
#pragma unroll
        for (int j = 0; j < 4; j++)
            xr[j][n] = (node < NN) ? g_h2[(size_t)node * D + j * 32 + lane] : 0.f;
    }
    float4 b0 = *(float4*)(bs + lane * 4);
    float4 b1 = *(float4*)(bs + 128 + lane * 4);
    float4 b2 = *(float4*)(bs + 256 + lane * 4);
    float4 a0[4], a1[4], a2[4];
#pragma unroll
    for (int n = 0; n < 4; n++) { a0[n] = b0; a1[n] = b1; a2[n] = b2; }

#pragma unroll
    for (int j = 0; j < 4; j++) {
#pragma unroll
        for (int kk = 0; kk < 32; kk++) {
            int k = j * 32 + kk;
            float4 w0 = *(float4*)(Ws + k * 384 + lane * 4);
            float4 w1 = *(float4*)(Ws + k * 384 + 128 + lane * 4);
            float4 w2 = *(float4*)(Ws + k * 384 + 256 + lane * 4);
#pragma unroll
            for (int n = 0; n < 4; n++) {
                float xv = __shfl_sync(0xffffffffu, xr[j][n], kk);
                a0[n].x += xv * w0.x; a0[n].y += xv * w0.y; a0[n].z += xv * w0.z; a0[n].w += xv * w0.w;
                a1[n].x += xv * w1.x; a1[n].y += xv * w1.y; a1[n].z += xv * w1.z; a1[n].w += xv * w1.w;
                a2[n].x += xv * w2.x; a2[n].y += xv * w2.y; a2[n].z += xv * w2.z; a2[n].w += xv * w2.w;
            }
        }
    }
#pragma unroll
    for (int n = 0; n < 4; n++) {
        int node = n0 + n;
        if (node < NN) {
            float* sp = out_s + (size_t)node * D + lane * 4;
            float4 s = *(float4*)sp;
            float4 ip = *(float4*)(g_ip + (size_t)node * D + lane * 4);
            s.x += a0[n].x + a1[n].x * ip.x;
            s.y += a0[n].y + a1[n].y * ip.y;
            s.z += a0[n].z + a1[n].z * ip.z;
            s.w += a0[n].w + a1[n].w * ip.w;
            *(float4*)sp = s;
            const float* uvb = g_uv + (size_t)node * 384 + lane * 4;
            float* ovb = out_v + (size_t)node * 384 + lane * 4;
#pragma unroll
            for (int ax = 0; ax < 3; ax++) {
                float4 uv = *(const float4*)(uvb + ax * 128);
                float4 vv = *(float4*)(ovb + ax * 128);
                vv.x += a2[n].x * uv.x;
                vv.y += a2[n].y * uv.y;
                vv.z += a2[n].z * uv.z;
                vv.w += a2[n].w * uv.w;
                *(float4*)(ovb + ax * 128) = vv;
            }
        }
    }
}

// ---------------- launch ------------------------------------------------------
extern "C" void kernel_launch(void* const* d_in, const int* in_sizes, int n_in,
                              void* d_out, int out_size) {
    const float* ns  = (const float*)d_in[0];
    const float* nv  = (const float*)d_in[1];
    const float* es  = (const float*)d_in[2];
    const float* ev  = (const float*)d_in[3];
    const float* en  = (const float*)d_in[4];
    const int*   ei  = (const int*)d_in[5];
    const float* Wf  = (const float*)d_in[6];
    const float* bf  = (const float*)d_in[7];
    const float* Wm1 = (const float*)d_in[8];
    const float* bm1 = (const float*)d_in[9];
    const float* Wm2 = (const float*)d_in[10];
    const float* bm2 = (const float*)d_in[11];
    const float* WU  = (const float*)d_in[12];
    const float* WV  = (const float*)d_in[13];
    const float* Wa1 = (const float*)d_in[14];
    const float* ba1 = (const float*)d_in[15];
    const float* Wa2 = (const float*)d_in[16];
    const float* ba2 = (const float*)d_in[17];
    float* out = (float*)d_out;

    const int SM_MLP1 = (16384 + 128 + 512) * 4;
    const int SM_GEMM = (49152 + 384) * 4;        // mlp2 / a2
    const int SM_UV   = (32768 + 4 * 384) * 4;
    const int SM_A1   = (32768 + 128) * 4;

    cudaFuncSetAttribute(k_mlp1, cudaFuncAttributeMaxDynamicSharedMemorySize, SM_MLP1);
    cudaFuncSetAttribute(k_mlp2, cudaFuncAttributeMaxDynamicSharedMemorySize, SM_GEMM);
    cudaFuncSetAttribute(k_uv,   cudaFuncAttributeMaxDynamicSharedMemorySize, SM_UV);
    cudaFuncSetAttribute(k_a1,   cudaFuncAttributeMaxDynamicSharedMemorySize, SM_A1);
    cudaFuncSetAttribute(k_a2,   cudaFuncAttributeMaxDynamicSharedMemorySize, SM_GEMM);

    int gnode = (NN + 63) / 64;   // 313

    k_init<<<2048, 256>>>(ns, nv, out);
    k_mlp1<<<148, 512, SM_MLP1>>>(ns, Wm1, bm1);
    k_mlp2<<<gnode, 512, SM_GEMM>>>(Wm2, bm2);
    k_edge<<<148, 768>>>(es, ev, en, ei, Wf, bf, nv, out);
    k_uv<<<148, 512, SM_UV>>>(WU, WV, out);
    k_a1<<<gnode, 512, SM_A1>>>(Wa1, ba1, out);
    k_a2<<<gnode, 512, SM_GEMM>>>(Wa2, ba2, out);
}

// round 5
// speedup vs baseline: 1.2893x; 1.2893x over previous
#include <cuda_runtime.h>

#define D      128
#define NN     20000
#define NE     600000
#define ESZ    20

// ---------------- scratch (device globals; no allocations allowed) ----------
__device__ float g_h1[NN * D];        // silu(s@Wm1+bm1)
__device__ float g_so[NN * 3 * D];    // scalar_output
__device__ float g_uv[NN * 3 * D];    // Uv
__device__ float g_vvsq[NN * D];      // sum_axis Vv^2
__device__ float g_ip[NN * D];        // sum_axis Uv*Vv
__device__ float g_h2[NN * D];        // silu([s,Vvsq]@Wa1+ba1)

__device__ __forceinline__ float silu_f(float x) {
    return x / (1.0f + __expf(-x));
}

__device__ __forceinline__ void red4(float* p, float a, float b, float c, float d) {
    asm volatile("red.global.add.v4.f32 [%0], {%1,%2,%3,%4};"
                 :: "l"(p), "f"(a), "f"(b), "f"(c), "f"(d) : "memory");
}

// ---------------- kernel 1: init output with residuals -----------------------
__global__ void k_init(const float* __restrict__ ns, const float* __restrict__ nv,
                       float* __restrict__ out) {
    const float4* a = (const float4*)ns;
    const float4* b = (const float4*)nv;
    float4* os = (float4*)out;
    float4* ov = os + (NN * D) / 4;
    const int ts = NN * D / 4;
    const int tv = NN * 3 * D / 4;
    for (int i = blockIdx.x * blockDim.x + threadIdx.x; i < ts; i += gridDim.x * blockDim.x)
        os[i] = a[i];
    for (int i = blockIdx.x * blockDim.x + threadIdx.x; i < tv; i += gridDim.x * blockDim.x)
        ov[i] = b[i];
}

// ---------------- kernel 2: h1 = silu(ns @ Wm1 + bm1)  (register-tiled) ------
__global__ void __launch_bounds__(512, 1)
k_mlp1(const float* __restrict__ x, const float* __restrict__ W,
       const float* __restrict__ b) {
    extern __shared__ float sm[];
    float* Ws = sm;                 // 16384
    float* bs = sm + 16384;         // 128
    int tid = threadIdx.x;
    {
        const float4* Wv = (const float4*)W;
        float4* Wsv = (float4*)Ws;
        for (int i = tid; i < 4096; i += 512) Wsv[i] = Wv[i];
        if (tid < 128) bs[tid] = b[tid];
    }
    __syncthreads();
    int warp = tid >> 5, lane = tid & 31;
    int n0 = blockIdx.x * 64 + warp * 4;

    float xr[4][4];
#pragma unroll
    for (int n = 0; n < 4; n++) {
        int node = n0 + n;
#pragma unroll
        for (int j = 0; j < 4; j++)
            xr[j][n] = (node < NN) ? x[(size_t)node * D + j * 32 + lane] : 0.f;
    }
    float4 bv = *(float4*)(bs + lane * 4);
    float4 acc[4];
#pragma unroll
    for (int n = 0; n < 4; n++) acc[n] = bv;

#pragma unroll
    for (int j = 0; j < 4; j++) {
#pragma unroll
        for (int kk = 0; kk < 32; kk++) {
            int k = j * 32 + kk;
            float4 w = *(float4*)(Ws + k * D + lane * 4);
#pragma unroll
            for (int n = 0; n < 4; n++) {
                float v = __shfl_sync(0xffffffffu, xr[j][n], kk);
                acc[n].x += v * w.x; acc[n].y += v * w.y;
                acc[n].z += v * w.z; acc[n].w += v * w.w;
            }
        }
    }
#pragma unroll
    for (int n = 0; n < 4; n++) {
        int node = n0 + n;
        if (node < NN) {
            float4 o;
            o.x = silu_f(acc[n].x); o.y = silu_f(acc[n].y);
            o.z = silu_f(acc[n].z); o.w = silu_f(acc[n].w);
            *(float4*)(g_h1 + (size_t)node * D + lane * 4) = o;
        }
    }
}

// ---------------- kernel 3: scalar_output = h1 @ Wm2 + bm2 -------------------
__global__ void __launch_bounds__(512, 1)
k_mlp2(const float* __restrict__ W, const float* __restrict__ b) {
    extern __shared__ float sm[];
    float* Ws = sm;                 // 49152
    float* bs = sm + 49152;         // 384
    int tid = threadIdx.x;
    {
        const float4* Wv = (const float4*)W;
        float4* Wsv = (float4*)Ws;
        for (int i = tid; i < 12288; i += 512) Wsv[i] = Wv[i];
        if (tid < 384) bs[tid] = b[tid];
    }
    __syncthreads();
    int warp = tid >> 5, lane = tid & 31;
    int n0 = blockIdx.x * 64 + warp * 4;

    float xr[4][4];
#pragma unroll
    for (int n = 0; n < 4; n++) {
        int node = n0 + n;
#pragma unroll
        for (int j = 0; j < 4; j++)
            xr[j][n] = (node < NN) ? g_h1[(size_t)node * D + j * 32 + lane] : 0.f;
    }
    float4 b0 = *(float4*)(bs + lane * 4);
    float4 b1 = *(float4*)(bs + 128 + lane * 4);
    float4 b2 = *(float4*)(bs + 256 + lane * 4);
    float4 a0[4], a1[4], a2[4];
#pragma unroll
    for (int n = 0; n < 4; n++) { a0[n] = b0; a1[n] = b1; a2[n] = b2; }

#pragma unroll
    for (int j = 0; j < 4; j++) {
#pragma unroll
        for (int kk = 0; kk < 32; kk++) {
            int k = j * 32 + kk;
            float4 w0 = *(float4*)(Ws + k * 384 + lane * 4);
            float4 w1 = *(float4*)(Ws + k * 384 + 128 + lane * 4);
            float4 w2 = *(float4*)(Ws + k * 384 + 256 + lane * 4);
#pragma unroll
            for (int n = 0; n < 4; n++) {
                float xv = __shfl_sync(0xffffffffu, xr[j][n], kk);
                a0[n].x += xv * w0.x; a0[n].y += xv * w0.y; a0[n].z += xv * w0.z; a0[n].w += xv * w0.w;
                a1[n].x += xv * w1.x; a1[n].y += xv * w1.y; a1[n].z += xv * w1.z; a1[n].w += xv * w1.w;
                a2[n].x += xv * w2.x; a2[n].y += xv * w2.y; a2[n].z += xv * w2.z; a2[n].w += xv * w2.w;
            }
        }
    }
#pragma unroll
    for (int n = 0; n < 4; n++) {
        int node = n0 + n;
        if (node < NN) {
            float* o = g_so + (size_t)node * 384 + lane * 4;
            *(float4*)o = a0[n];
            *(float4*)(o + 128) = a1[n];
            *(float4*)(o + 256) = a2[n];
        }
    }
}

// ---------------- kernel 4: fused edge filter + gather + scatter -------------
// 3 independent role-warps per edge (float4 lanes), 2-deep software pipeline:
//   scalar loads (es/ei/en) issued 2 edges ahead; gathers (so/nv/ev) 1 ahead.
__global__ void __launch_bounds__(384, 1)
k_edge(const float* __restrict__ es, const float* __restrict__ ev,
       const float* __restrict__ en, const int* __restrict__ ei,
       const float* __restrict__ Wf, const float* __restrict__ bf,
       const float* __restrict__ nv, float* __restrict__ out) {
    int gwarp = (blockIdx.x * blockDim.x + threadIdx.x) >> 5;
    int lane = threadIdx.x & 31;
    int trio = gwarp / 3, role = gwarp % 3;
    const int step = (gridDim.x * 384 / 32) / 3;   // 592
    if (trio >= step) return;

    float4 Wreg[ESZ];
    const float* wb = Wf + role * 128 + lane * 4;
#pragma unroll
    for (int k = 0; k < ESZ; k++) Wreg[k] = *(const float4*)(wb + k * 384);
    float4 bfr = *(const float4*)(bf + role * 128 + lane * 4);

    float* out_s = out;
    float* out_v = out + (size_t)NN * D;

    int e = trio;
    if (e >= NE) return;

    // ---- prologue: scalars for e and e+step, gathers for e ----
    float esvA = (lane < ESZ) ? __ldg(es + (size_t)e * ESZ + lane) : 0.f;
    int2 sdA = __ldg((const int2*)ei + e);
    float rA = __ldg(en + e);

    int e1 = e + step;
    bool hasB = e1 < NE;
    float esvB = 0.f; int2 sdB = {0, 0}; float rB = 9.f;
    if (hasB) {
        esvB = (lane < ESZ) ? __ldg(es + (size_t)e1 * ESZ + lane) : 0.f;
        sdB = __ldg((const int2*)ei + e1);
        rB = __ldg(en + e1);
    }

    float4 soA = __ldg((const float4*)(g_so + (size_t)sdA.x * 384 + role * 128) + lane);
    float4 nA0 = {0,0,0,0}, nA1 = {0,0,0,0}, nA2 = {0,0,0,0};
    float evA0 = 0.f, evA1 = 0.f, evA2 = 0.f;
    if (role == 0) {
        const float4* nvp = (const float4*)(nv + (size_t)sdA.x * 384) + lane;
        nA0 = __ldg(nvp); nA1 = __ldg(nvp + 32); nA2 = __ldg(nvp + 64);
    } else if (role == 1) {
        evA0 = __ldg(ev + 3 * (size_t)e);
        evA1 = __ldg(ev + 3 * (size_t)e + 1);
        evA2 = __ldg(ev + 3 * (size_t)e + 2);
    }

    while (true) {
        // ---- stage 1: issue scalar loads for e+2*step ----
        int e2 = e1 + step;
        float esvC = 0.f; int2 sdC = {0, 0}; float rC = 9.f;
        if (e2 < NE) {
            esvC = (lane < ESZ) ? __ldg(es + (size_t)e2 * ESZ + lane) : 0.f;
            sdC = __ldg((const int2*)ei + e2);
            rC = __ldg(en + e2);
        }
        // ---- stage 2: issue gathers for e+step ----
        float4 soB = {0,0,0,0};
        float4 nB0 = {0,0,0,0}, nB1 = {0,0,0,0}, nB2 = {0,0,0,0};
        float evB0 = 0.f, evB1 = 0.f, evB2 = 0.f;
        if (hasB) {
            soB = __ldg((const float4*)(g_so + (size_t)sdB.x * 384 + role * 128) + lane);
            if (role == 0) {
                const float4* nvp = (const float4*)(nv + (size_t)sdB.x * 384) + lane;
                nB0 = __ldg(nvp); nB1 = __ldg(nvp + 32); nB2 = __ldg(nvp + 64);
            } else if (role == 1) {
                evB0 = __ldg(ev + 3 * (size_t)e1);
                evB1 = __ldg(ev + 3 * (size_t)e1 + 1);
                evB2 = __ldg(ev + 3 * (size_t)e1 + 2);
            }
        }
        // ---- stage 3: compute + scatter current edge ----
        float fc = (rA < 5.0f) ? 0.5f * (cospif(rA * 0.2f) + 1.0f) : 0.0f;
        float4 f = bfr;
#pragma unroll
        for (int k = 0; k < ESZ; k++) {
            float ek = __shfl_sync(0xffffffffu, esvA, k);
            f.x += ek * Wreg[k].x;
            f.y += ek * Wreg[k].y;
            f.z += ek * Wreg[k].z;
            f.w += ek * Wreg[k].w;
        }
        float4 m;
        m.x = f.x * fc * soA.x;
        m.y = f.y * fc * soA.y;
        m.z = f.z * fc * soA.z;
        m.w = f.w * fc * soA.w;
        int dst = sdA.y;

        if (role == 2) {
            red4(out_s + (size_t)dst * D + lane * 4, m.x, m.y, m.z, m.w);
        } else if (role == 1) {
            float* ovb = out_v + (size_t)dst * 384 + lane * 4;
            red4(ovb,       m.x * evA0, m.y * evA0, m.z * evA0, m.w * evA0);
            red4(ovb + 128, m.x * evA1, m.y * evA1, m.z * evA1, m.w * evA1);
            red4(ovb + 256, m.x * evA2, m.y * evA2, m.z * evA2, m.w * evA2);
        } else {
            float* ovb = out_v + (size_t)dst * 384 + lane * 4;
            red4(ovb,       m.x * nA0.x, m.y * nA0.y, m.z * nA0.z, m.w * nA0.w);
            red4(ovb + 128, m.x * nA1.x, m.y * nA1.y, m.z * nA1.z, m.w * nA1.w);
            red4(ovb + 256, m.x * nA2.x, m.y * nA2.y, m.z * nA2.z, m.w * nA2.w);
        }
        // ---- rotate pipeline ----
        if (!hasB) break;
        e = e1; e1 = e2;
        esvA = esvB; sdA = sdB; rA = rB;
        soA = soB; nA0 = nB0; nA1 = nB1; nA2 = nB2;
        evA0 = evB0; evA1 = evB1; evA2 = evB2;
        esvB = esvC; sdB = sdC; rB = rC;
        hasB = e1 < NE;
    }
}

// ---------------- kernel 5: Uv, |Vv|^2, <Uv,Vv>  (register-tiled) ------------
// warp = 2 nodes; lane owns 4 cols; WU+WV in smem (128 KB)
__global__ void __launch_bounds__(512, 1)
k_uv(const float* __restrict__ WU, const float* __restrict__ WV,
     const float* __restrict__ out) {
    extern __shared__ float sm[];
    float* WUs = sm;
    float* WVs = sm + 16384;
    const float* v_in = out + (size_t)NN * D;
    int tid = threadIdx.x;
    {
        const float4* u4 = (const float4*)WU;
        const float4* v4 = (const float4*)WV;
        float4* su = (float4*)WUs;
        float4* sv = (float4*)WVs;
        for (int i = tid; i < 4096; i += 512) { su[i] = u4[i]; sv[i] = v4[i]; }
    }
    __syncthreads();
    int warp = tid >> 5, lane = tid & 31;
    int n0 = blockIdx.x * 32 + warp * 2;

    float xr[3][4][2];
#pragma unroll
    for (int n = 0; n < 2; n++) {
        int node = n0 + n;
#pragma unroll
        for (int ax = 0; ax < 3; ax++)
#pragma unroll
            for (int j = 0; j < 4; j++)
                xr[ax][j][n] = (node < NN)
                    ? v_in[(size_t)node * 384 + ax * 128 + j * 32 + lane] : 0.f;
    }
    float4 aU[3][2], aV[3][2];
#pragma unroll
    for (int ax = 0; ax < 3; ax++)
#pragma unroll
        for (int n = 0; n < 2; n++) {
            aU[ax][n] = make_float4(0, 0, 0, 0);
            aV[ax][n] = make_float4(0, 0, 0, 0);
        }

#pragma unroll
    for (int j = 0; j < 4; j++) {
#pragma unroll
        for (int kk = 0; kk < 32; kk++) {
            int k = j * 32 + kk;
            float4 wu = *(float4*)(WUs + k * D + lane * 4);
            float4 wv = *(float4*)(WVs + k * D + lane * 4);
#pragma unroll
            for (int n = 0; n < 2; n++) {
#pragma unroll
                for (int ax = 0; ax < 3; ax++) {
                    float v = __shfl_sync(0xffffffffu, xr[ax][j][n], kk);
                    aU[ax][n].x += v * wu.x; aU[ax][n].y += v * wu.y;
                    aU[ax][n].z += v * wu.z; aU[ax][n].w += v * wu.w;
                    aV[ax][n].x += v * wv.x; aV[ax][n].y += v * wv.y;
                    aV[ax][n].z += v * wv.z; aV[ax][n].w += v * wv.w;
                }
            }
        }
    }
#pragma unroll
    for (int n = 0; n < 2; n++) {
        int node = n0 + n;
        if (node < NN) {
#pragma unroll
            for (int ax = 0; ax < 3; ax++)
                *(float4*)(g_uv + (size_t)node * 384 + ax * 128 + lane * 4) = aU[ax][n];
            float4 vq, ip;
            vq.x = aV[0][n].x * aV[0][n].x + aV[1][n].x * aV[1][n].x + aV[2][n].x * aV[2][n].x;
            vq.y = aV[0][n].y * aV[0][n].y + aV[1][n].y * aV[1][n].y + aV[2][n].y * aV[2][n].y;
            vq.z = aV[0][n].z * aV[0][n].z + aV[1][n].z * aV[1][n].z + aV[2][n].z * aV[2][n].z;
            vq.w = aV[0][n].w * aV[0][n].w + aV[1][n].w * aV[1][n].w + aV[2][n].w * aV[2][n].w;
            ip.x = aU[0][n].x * aV[0][n].x + aU[1][n].x * aV[1][n].x + aU[2][n].x * aV[2][n].x;
            ip.y = aU[0][n].y * aV[0][n].y + aU[1][n].y * aV[1][n].y + aU[2][n].y * aV[2][n].y;
            ip.z = aU[0][n].z * aV[0][n].z + aU[1][n].z * aV[1][n].z + aU[2][n].z * aV[2][n].z;
            ip.w = aU[0][n].w * aV[0][n].w + aU[1][n].w * aV[1][n].w + aU[2][n].w * aV[2][n].w;
            *(float4*)(g_vvsq + (size_t)node * D + lane * 4) = vq;
            *(float4*)(g_ip + (size_t)node * D + lane * 4) = ip;
        }
    }
}

// ---------------- kernel 6: h2 = silu([s, Vvsq] @ Wa1 + ba1) -----------------
__global__ void __launch_bounds__(512, 1)
k_a1(const float* __restrict__ W, const float* __restrict__ b,
     const float* __restrict__ out) {
    extern __shared__ float sm[];
    float* Ws = sm;                 // 32768
    float* bs = sm + 32768;         // 128
    int tid = threadIdx.x;
    {
        const float4* Wv = (const float4*)W;
        float4* Wsv = (float4*)Ws;
        for (int i = tid; i < 8192; i += 512) Wsv[i] = Wv[i];
        if (tid < 128) bs[tid] = b[tid];
    }
    __syncthreads();
    int warp = tid >> 5, lane = tid & 31;
    int n0 = blockIdx.x * 64 + warp * 4;

    float xr[8][4];
#pragma unroll
    for (int n = 0; n < 4; n++) {
        int node = n0 + n;
        if (node < NN) {
#pragma unroll
            for (int j = 0; j < 4; j++)
                xr[j][n] = out[(size_t)node * D + j * 32 + lane];
#pragma unroll
            for (int j = 0; j < 4; j++)
                xr[4 + j][n] = g_vvsq[(size_t)node * D + j * 32 + lane];
        } else {
#pragma unroll
            for (int j = 0; j < 8; j++) xr[j][n] = 0.f;
        }
    }
    float4 bv = *(float4*)(bs + lane * 4);
    float4 acc[4];
#pragma unroll
    for (int n = 0; n < 4; n++) acc[n] = bv;

#pragma unroll
    for (int j = 0; j < 8; j++) {
#pragma unroll
        for (int kk = 0; kk < 32; kk++) {
            int k = j * 32 + kk;
            float4 w = *(float4*)(Ws + k * D + lane * 4);
#pragma unroll
            for (int n = 0; n < 4; n++) {
                float xv = __shfl_sync(0xffffffffu, xr[j][n], kk);
                acc[n].x += xv * w.x; acc[n].y += xv * w.y;
                acc[n].z += xv * w.z; acc[n].w += xv * w.w;
            }
        }
    }
#pragma unroll
    for (int n = 0; n < 4; n++) {
        int node = n0 + n;
        if (node < NN) {
            float4 o;
            o.x = silu_f(acc[n].x); o.y = silu_f(acc[n].y);
            o.z = silu_f(acc[n].z); o.w = silu_f(acc[n].w);
            *(float4*)(g_h2 + (size_t)node * D + lane * 4) = o;
        }
    }
}

// ---------------- kernel 7: a = h2 @ Wa2 + ba2, final in-place update --------
__global__ void __launch_bounds__(512, 1)
k_a2(const float* __restrict__ W, const float* __restrict__ b,
     float* __restrict__ out) {
    extern __shared__ float sm[];
    float* Ws = sm;                 // 49152
    float* bs = sm + 49152;         // 384
    int tid = threadIdx.x;
    {
        const float4* Wv = (const float4*)W;
        float4* Wsv = (float4*)Ws;
        for (int i = tid; i < 12288; i += 512) Wsv[i] = Wv[i];
        if (tid < 384) bs[tid] = b[tid];
    }
    __syncthreads();
    int warp = tid >> 5, lane = tid & 31;
    int n0 = blockIdx.x * 64 + warp * 4;
    float* out_s = out;
    float* out_v = out + (size_t)NN * D;

    float xr[4][4];
#pragma unroll
    for (int n = 0; n < 4; n++) {
        int node = n0 + n;
#pragma unroll
        for (int j = 0; j < 4; j++)
            xr[j][n] = (node < NN) ? g_h2[(size_t)node * D + j * 32 + lane] : 0.f;
    }
    float4 b0 = *(float4*)(bs + lane * 4);
    float4 b1 = *(float4*)(bs + 128 + lane * 4);
    float4 b2 = *(float4*)(bs + 256 + lane * 4);
    float4 a0[4], a1[4], a2[4];
#pragma unroll
    for (int n = 0; n < 4; n++) { a0[n] = b0; a1[n] = b1; a2[n] = b2; }

#pragma unroll
    for (int j = 0; j < 4; j++) {
#pragma unroll
        for (int kk = 0; kk < 32; kk++) {
            int k = j * 32 + kk;
            float4 w0 = *(float4*)(Ws + k * 384 + lane * 4);
            float4 w1 = *(float4*)(Ws + k * 384 + 128 + lane * 4);
            float4 w2 = *(float4*)(Ws + k * 384 + 256 + lane * 4);
#pragma unroll
            for (int n = 0; n < 4; n++) {
                float xv = __shfl_sync(0xffffffffu, xr[j][n], kk);
                a0[n].x += xv * w0.x; a0[n].y += xv * w0.y; a0[n].z += xv * w0.z; a0[n].w += xv * w0.w;
                a1[n].x += xv * w1.x; a1[n].y += xv * w1.y; a1[n].z += xv * w1.z; a1[n].w += xv * w1.w;
                a2[n].x += xv * w2.x; a2[n].y += xv * w2.y; a2[n].z += xv * w2.z; a2[n].w += xv * w2.w;
            }
        }
    }
#pragma unroll
    for (int n = 0; n < 4; n++) {
        int node = n0 + n;
        if (node < NN) {
            float* sp = out_s + (size_t)node * D + lane * 4;
            float4 s = *(float4*)sp;
            float4 ip = *(float4*)(g_ip + (size_t)node * D + lane * 4);
            s.x += a0[n].x + a1[n].x * ip.x;
            s.y += a0[n].y + a1[n].y * ip.y;
            s.z += a0[n].z + a1[n].z * ip.z;
            s.w += a0[n].w + a1[n].w * ip.w;
            *(float4*)sp = s;
            const float* uvb = g_uv + (size_t)node * 384 + lane * 4;
            float* ovb = out_v + (size_t)node * 384 + lane * 4;
#pragma unroll
            for (int ax = 0; ax < 3; ax++) {
                float4 uv = *(const float4*)(uvb + ax * 128);
                float4 vv = *(float4*)(ovb + ax * 128);
                vv.x += a2[n].x * uv.x;
                vv.y += a2[n].y * uv.y;
                vv.z += a2[n].z * uv.z;
                vv.w += a2[n].w * uv.w;
                *(float4*)(ovb + ax * 128) = vv;
            }
        }
    }
}

// ---------------- launch ------------------------------------------------------
extern "C" void kernel_launch(void* const* d_in, const int* in_sizes, int n_in,
                              void* d_out, int out_size) {
    const float* ns  = (const float*)d_in[0];
    const float* nv  = (const float*)d_in[1];
    const float* es  = (const float*)d_in[2];
    const float* ev  = (const float*)d_in[3];
    const float* en  = (const float*)d_in[4];
    const int*   ei  = (const int*)d_in[5];
    const float* Wf  = (const float*)d_in[6];
    const float* bf  = (const float*)d_in[7];
    const float* Wm1 = (const float*)d_in[8];
    const float* bm1 = (const float*)d_in[9];
    const float* Wm2 = (const float*)d_in[10];
    const float* bm2 = (const float*)d_in[11];
    const float* WU  = (const float*)d_in[12];
    const float* WV  = (const float*)d_in[13];
    const float* Wa1 = (const float*)d_in[14];
    const float* ba1 = (const float*)d_in[15];
    const float* Wa2 = (const float*)d_in[16];
    const float* ba2 = (const float*)d_in[17];
    float* out = (float*)d_out;

    const int SM_MLP1 = (16384 + 128) * 4;
    const int SM_GEMM = (49152 + 384) * 4;        // mlp2 / a2
    const int SM_UV   = 32768 * 4;
    const int SM_A1   = (32768 + 128) * 4;

    cudaFuncSetAttribute(k_mlp1, cudaFuncAttributeMaxDynamicSharedMemorySize, SM_MLP1);
    cudaFuncSetAttribute(k_mlp2, cudaFuncAttributeMaxDynamicSharedMemorySize, SM_GEMM);
    cudaFuncSetAttribute(k_uv,   cudaFuncAttributeMaxDynamicSharedMemorySize, SM_UV);
    cudaFuncSetAttribute(k_a1,   cudaFuncAttributeMaxDynamicSharedMemorySize, SM_A1);
    cudaFuncSetAttribute(k_a2,   cudaFuncAttributeMaxDynamicSharedMemorySize, SM_GEMM);

    int gnode = (NN + 63) / 64;   // 313
    int guv   = (NN + 31) / 32;   // 625

    k_init<<<2048, 256>>>(ns, nv, out);
    k_mlp1<<<gnode, 512, SM_MLP1>>>(ns, Wm1, bm1);
    k_mlp2<<<gnode, 512, SM_GEMM>>>(Wm2, bm2);
    k_edge<<<148, 384>>>(es, ev, en, ei, Wf, bf, nv, out);
    k_uv<<<guv, 512, SM_UV>>>(WU, WV, out);
    k_a1<<<gnode, 512, SM_A1>>>(Wa1, ba1, out);
    k_a2<<<gnode, 512, SM_GEMM>>>(Wa2, ba2, out);
}

// round 7
// speedup vs baseline: 1.3520x; 1.0486x over previous
#include <cuda_runtime.h>

#define D      128
#define NN     20000
#define NE     600000
#define ESZ    20

// ---------------- scratch (device globals; no allocations allowed) ----------
__device__ float g_h1[NN * D];        // silu(s@Wm1+bm1)
__device__ float g_so[NN * 3 * D];    // scalar_output
__device__ float g_uv[NN * 3 * D];    // Uv
__device__ float g_vvsq[NN * D];      // sum_axis Vv^2
__device__ float g_ip[NN * D];        // sum_axis Uv*Vv
__device__ float g_h2[NN * D];        // silu([s,Vvsq]@Wa1+ba1)

__device__ __forceinline__ float silu_f(float x) {
    return x / (1.0f + __expf(-x));
}

__device__ __forceinline__ void red4(float* p, float a, float b, float c, float d) {
    asm volatile("red.global.add.v4.f32 [%0], {%1,%2,%3,%4};"
                 :: "l"(p), "f"(a), "f"(b), "f"(c), "f"(d) : "memory");
}
__device__ __forceinline__ void red2(float* p, float a, float b) {
    asm volatile("red.global.add.v2.f32 [%0], {%1,%2};"
                 :: "l"(p), "f"(a), "f"(b) : "memory");
}

// ---------------- kernel 1: init output with residuals -----------------------
__global__ void k_init(const float* __restrict__ ns, const float* __restrict__ nv,
                       float* __restrict__ out) {
    const float4* a = (const float4*)ns;
    const float4* b = (const float4*)nv;
    float4* os = (float4*)out;
    float4* ov = os + (NN * D) / 4;
    const int ts = NN * D / 4;
    const int tv = NN * 3 * D / 4;
    for (int i = blockIdx.x * blockDim.x + threadIdx.x; i < ts; i += gridDim.x * blockDim.x)
        os[i] = a[i];
    for (int i = blockIdx.x * blockDim.x + threadIdx.x; i < tv; i += gridDim.x * blockDim.x)
        ov[i] = b[i];
}

// ---------------- kernel 2: h1 = silu(ns @ Wm1 + bm1)  (register-tiled) ------
__global__ void __launch_bounds__(512, 1)
k_mlp1(const float* __restrict__ x, const float* __restrict__ W,
       const float* __restrict__ b) {
    extern __shared__ float sm[];
    float* Ws = sm;                 // 16384
    float* bs = sm + 16384;         // 128
    int tid = threadIdx.x;
    {
        const float4* Wv = (const float4*)W;
        float4* Wsv = (float4*)Ws;
        for (int i = tid; i < 4096; i += 512) Wsv[i] = Wv[i];
        if (tid < 128) bs[tid] = b[tid];
    }
    __syncthreads();
    int warp = tid >> 5, lane = tid & 31;
    int n0 = blockIdx.x * 64 + warp * 4;

    float xr[4][4];
#pragma unroll
    for (int n = 0; n < 4; n++) {
        int node = n0 + n;
#pragma unroll
        for (int j = 0; j < 4; j++)
            xr[j][n] = (node < NN) ? x[(size_t)node * D + j * 32 + lane] : 0.f;
    }
    float4 bv = *(float4*)(bs + lane * 4);
    float4 acc[4];
#pragma unroll
    for (int n = 0; n < 4; n++) acc[n] = bv;

#pragma unroll
    for (int j = 0; j < 4; j++) {
#pragma unroll
        for (int kk = 0; kk < 32; kk++) {
            int k = j * 32 + kk;
            float4 w = *(float4*)(Ws + k * D + lane * 4);
#pragma unroll
            for (int n = 0; n < 4; n++) {
                float v = __shfl_sync(0xffffffffu, xr[j][n], kk);
                acc[n].x += v * w.x; acc[n].y += v * w.y;
                acc[n].z += v * w.z; acc[n].w += v * w.w;
            }
        }
    }
#pragma unroll
    for (int n = 0; n < 4; n++) {
        int node = n0 + n;
        if (node < NN) {
            float4 o;
            o.x = silu_f(acc[n].x); o.y = silu_f(acc[n].y);
            o.z = silu_f(acc[n].z); o.w = silu_f(acc[n].w);
            *(float4*)(g_h1 + (size_t)node * D + lane * 4) = o;
        }
    }
}

// ---------------- kernel 3: scalar_output = h1 @ Wm2 + bm2 -------------------
__global__ void __launch_bounds__(512, 1)
k_mlp2(const float* __restrict__ W, const float* __restrict__ b) {
    extern __shared__ float sm[];
    float* Ws = sm;                 // 49152
    float* bs = sm + 49152;         // 384
    int tid = threadIdx.x;
    {
        const float4* Wv = (const float4*)W;
        float4* Wsv = (float4*)Ws;
        for (int i = tid; i < 12288; i += 512) Wsv[i] = Wv[i];
        if (tid < 384) bs[tid] = b[tid];
    }
    __syncthreads();
    int warp = tid >> 5, lane = tid & 31;
    int n0 = blockIdx.x * 64 + warp * 4;

    float xr[4][4];
#pragma unroll
    for (int n = 0; n < 4; n++) {
        int node = n0 + n;
#pragma unroll
        for (int j = 0; j < 4; j++)
            xr[j][n] = (node < NN) ? g_h1[(size_t)node * D + j * 32 + lane] : 0.f;
    }
    float4 b0 = *(float4*)(bs + lane * 4);
    float4 b1 = *(float4*)(bs + 128 + lane * 4);
    float4 b2 = *(float4*)(bs + 256 + lane * 4);
    float4 a0[4], a1[4], a2[4];
#pragma unroll
    for (int n = 0; n < 4; n++) { a0[n] = b0; a1[n] = b1; a2[n] = b2; }

#pragma unroll
    for (int j = 0; j < 4; j++) {
#pragma unroll
        for (int kk = 0; kk < 32; kk++) {
            int k = j * 32 + kk;
            float4 w0 = *(float4*)(Ws + k * 384 + lane * 4);
            float4 w1 = *(float4*)(Ws + k * 384 + 128 + lane * 4);
            float4 w2 = *(float4*)(Ws + k * 384 + 256 + lane * 4);
#pragma unroll
            for (int n = 0; n < 4; n++) {
                float xv = __shfl_sync(0xffffffffu, xr[j][n], kk);
                a0[n].x += xv * w0.x; a0[n].y += xv * w0.y; a0[n].z += xv * w0.z; a0[n].w += xv * w0.w;
                a1[n].x += xv * w1.x; a1[n].y += xv * w1.y; a1[n].z += xv * w1.z; a1[n].w += xv * w1.w;
                a2[n].x += xv * w2.x; a2[n].y += xv * w2.y; a2[n].z += xv * w2.z; a2[n].w += xv * w2.w;
            }
        }
    }
#pragma unroll
    for (int n = 0; n < 4; n++) {
        int node = n0 + n;
        if (node < NN) {
            float* o = g_so + (size_t)node * 384 + lane * 4;
            *(float4*)o = a0[n];
            *(float4*)(o + 128) = a1[n];
            *(float4*)(o + 256) = a2[n];
        }
    }
}

// ---------------- kernel 4: fused edge filter + gather + scatter -------------
// 3 independent warps per edge:
//   role 0/1 ("vector-half" h): lane owns ch = h*64+lane*2; holds BOTH gate_n
//     and gate_e weight slices; combines gate_n*nv[src] + gate_e*ev in regs and
//     issues 3 red2 (out_v atomic traffic halved vs separate roles).
//   role 2: messages_scalar, float4 lanes, 1 red4.
// 2-deep software pipeline: scalars 2 edges ahead, gathers 1 ahead.
__global__ void __launch_bounds__(384, 1)
k_edge(const float* __restrict__ es, const float* __restrict__ ev,
       const float* __restrict__ en, const int* __restrict__ ei,
       const float* __restrict__ Wf, const float* __restrict__ bf,
       const float* __restrict__ nv, float* __restrict__ out) {
    int gwarp = (blockIdx.x * blockDim.x + threadIdx.x) >> 5;
    int lane = threadIdx.x & 31;
    int trio = gwarp / 3, role = gwarp % 3;
    const int step = (gridDim.x * 384 / 32) / 3;   // 592
    if (trio >= NE) return;

    float* out_s = out;
    float* out_v = out + (size_t)NN * D;

    if (role == 2) {
        // ---------- scalar path: cols 256..383 ----------
        float4 Wreg[ESZ];
        const float* wb = Wf + 256 + lane * 4;
#pragma unroll
        for (int k = 0; k < ESZ; k++) Wreg[k] = *(const float4*)(wb + k * 384);
        float4 bfr = *(const float4*)(bf + 256 + lane * 4);

        int e = trio;
        float esvA = (lane < ESZ) ? __ldg(es + (size_t)e * ESZ + lane) : 0.f;
        int2 sdA = __ldg((const int2*)ei + e);
        float rA = __ldg(en + e);

        int e1 = e + step;
        bool hasB = e1 < NE;
        float esvB = 0.f; int2 sdB = {0, 0}; float rB = 9.f;
        if (hasB) {
            esvB = (lane < ESZ) ? __ldg(es + (size_t)e1 * ESZ + lane) : 0.f;
            sdB = __ldg((const int2*)ei + e1);
            rB = __ldg(en + e1);
        }
        float4 soA = __ldg((const float4*)(g_so + (size_t)sdA.x * 384 + 256) + lane);

        while (true) {
            int e2 = e1 + step;
            float esvC = 0.f; int2 sdC = {0, 0}; float rC = 9.f;
            if (e2 < NE) {
                esvC = (lane < ESZ) ? __ldg(es + (size_t)e2 * ESZ + lane) : 0.f;
                sdC = __ldg((const int2*)ei + e2);
                rC = __ldg(en + e2);
            }
            float4 soB = {0,0,0,0};
            if (hasB)
                soB = __ldg((const float4*)(g_so + (size_t)sdB.x * 384 + 256) + lane);

            float fc = (rA < 5.0f) ? 0.5f * (cospif(rA * 0.2f) + 1.0f) : 0.0f;
            float4 f = bfr;
#pragma unroll
            for (int k = 0; k < ESZ; k++) {
                float ek = __shfl_sync(0xffffffffu, esvA, k);
                f.x += ek * Wreg[k].x;
                f.y += ek * Wreg[k].y;
                f.z += ek * Wreg[k].z;
                f.w += ek * Wreg[k].w;
            }
            red4(out_s + (size_t)sdA.y * D + lane * 4,
                 f.x * fc * soA.x, f.y * fc * soA.y,
                 f.z * fc * soA.z, f.w * fc * soA.w);

            if (!hasB) break;
            e = e1; e1 = e2;
            esvA = esvB; sdA = sdB; rA = rB; soA = soB;
            esvB = esvC; sdB = sdC; rB = rC;
            hasB = e1 < NE;
        }
    } else {
        // ---------- vector-half path: channels ch..ch+1 ----------
        int ch = role * 64 + lane * 2;
        float2 WN[ESZ], WE[ESZ];
#pragma unroll
        for (int k = 0; k < ESZ; k++) {
            WN[k] = *(const float2*)(Wf + k * 384 + ch);
            WE[k] = *(const float2*)(Wf + k * 384 + 128 + ch);
        }
        float2 bN = *(const float2*)(bf + ch);
        float2 bE = *(const float2*)(bf + 128 + ch);

        int e = trio;
        float esvA = (lane < ESZ) ? __ldg(es + (size_t)e * ESZ + lane) : 0.f;
        int2 sdA = __ldg((const int2*)ei + e);
        float rA = __ldg(en + e);

        int e1 = e + step;
        bool hasB = e1 < NE;
        float esvB = 0.f; int2 sdB = {0, 0}; float rB = 9.f;
        if (hasB) {
            esvB = (lane < ESZ) ? __ldg(es + (size_t)e1 * ESZ + lane) : 0.f;
            sdB = __ldg((const int2*)ei + e1);
            rB = __ldg(en + e1);
        }
        // gathers for edge A
        float2 soNA = __ldg((const float2*)(g_so + (size_t)sdA.x * 384 + ch));
        float2 soEA = __ldg((const float2*)(g_so + (size_t)sdA.x * 384 + 128 + ch));
        const float* nvbA = nv + (size_t)sdA.x * 384 + ch;
        float2 nA0 = __ldg((const float2*)nvbA);
        float2 nA1 = __ldg((const float2*)(nvbA + 128));
        float2 nA2 = __ldg((const float2*)(nvbA + 256));
        float evA0 = __ldg(ev + 3 * (size_t)e);
        float evA1 = __ldg(ev + 3 * (size_t)e + 1);
        float evA2 = __ldg(ev + 3 * (size_t)e + 2);

        while (true) {
            int e2 = e1 + step;
            float esvC = 0.f; int2 sdC = {0, 0}; float rC = 9.f;
            if (e2 < NE) {
                esvC = (lane < ESZ) ? __ldg(es + (size_t)e2 * ESZ + lane) : 0.f;
                sdC = __ldg((const int2*)ei + e2);
                rC = __ldg(en + e2);
            }
            float2 soNB = {0,0}, soEB = {0,0};
            float2 nB0 = {0,0}, nB1 = {0,0}, nB2 = {0,0};
            float evB0 = 0.f, evB1 = 0.f, evB2 = 0.f;
            if (hasB) {
                soNB = __ldg((const float2*)(g_so + (size_t)sdB.x * 384 + ch));
                soEB = __ldg((const float2*)(g_so + (size_t)sdB.x * 384 + 128 + ch));
                const float* nvbB = nv + (size_t)sdB.x * 384 + ch;
                nB0 = __ldg((const float2*)nvbB);
                nB1 = __ldg((const float2*)(nvbB + 128));
                nB2 = __ldg((const float2*)(nvbB + 256));
                evB0 = __ldg(ev + 3 * (size_t)e1);
                evB1 = __ldg(ev + 3 * (size_t)e1 + 1);
                evB2 = __ldg(ev + 3 * (size_t)e1 + 2);
            }
            float fc = (rA < 5.0f) ? 0.5f * (cospif(rA * 0.2f) + 1.0f) : 0.0f;
            float fNx = bN.x, fNy = bN.y, fEx = bE.x, fEy = bE.y;
#pragma unroll
            for (int k = 0; k < ESZ; k++) {
                float ek = __shfl_sync(0xffffffffu, esvA, k);
                fNx += ek * WN[k].x; fNy += ek * WN[k].y;
                fEx += ek * WE[k].x; fEy += ek * WE[k].y;
            }
            float gnx = fNx * fc * soNA.x, gny = fNy * fc * soNA.y;
            float gex = fEx * fc * soEA.x, gey = fEy * fc * soEA.y;
            float* ovb = out_v + (size_t)sdA.y * 384 + ch;
            red2(ovb,       gnx * nA0.x + gex * evA0, gny * nA0.y + gey * evA0);
            red2(ovb + 128, gnx * nA1.x + gex * evA1, gny * nA1.y + gey * evA1);
            red2(ovb + 256, gnx * nA2.x + gex * evA2, gny * nA2.y + gey * evA2);

            if (!hasB) break;
            e = e1; e1 = e2;
            esvA = esvB; sdA = sdB; rA = rB;
            soNA = soNB; soEA = soEB;
            nA0 = nB0; nA1 = nB1; nA2 = nB2;
            evA0 = evB0; evA1 = evB1; evA2 = evB2;
            esvB = esvC; sdB = sdC; rB = rC;
            hasB = e1 < NE;
        }
    }
}

// ---------------- kernel 5: Uv, |Vv|^2, <Uv,Vv>  (register-tiled) ------------
__global__ void __launch_bounds__(512, 1)
k_uv(const float* __restrict__ WU, const float* __restrict__ WV,
     const float* __restrict__ out) {
    extern __shared__ float sm[];
    float* WUs = sm;
    float* WVs = sm + 16384;
    const float* v_in = out + (size_t)NN * D;
    int tid = threadIdx.x;
    {
        const float4* u4 = (const float4*)WU;
        const float4* v4 = (const float4*)WV;
        float4* su = (float4*)WUs;
        float4* sv = (float4*)WVs;
        for (int i = tid; i < 4096; i += 512) { su[i] = u4[i]; sv[i] = v4[i]; }
    }
    __syncthreads();
    int warp = tid >> 5, lane = tid & 31;
    int n0 = blockIdx.x * 32 + warp * 2;

    float xr[3][4][2];
#pragma unroll
    for (int n = 0; n < 2; n++) {
        int node = n0 + n;
#pragma unroll
        for (int ax = 0; ax < 3; ax++)
#pragma unroll
            for (int j = 0; j < 4; j++)
                xr[ax][j][n] = (node < NN)
                    ? v_in[(size_t)node * 384 + ax * 128 + j * 32 + lane] : 0.f;
    }
    float4 aU[3][2], aV[3][2];
#pragma unroll
    for (int ax = 0; ax < 3; ax++)
#pragma unroll
        for (int n = 0; n < 2; n++) {
            aU[ax][n] = make_float4(0, 0, 0, 0);
            aV[ax][n] = make_float4(0, 0, 0, 0);
        }

#pragma unroll
    for (int j = 0; j < 4; j++) {
#pragma unroll
        for (int kk = 0; kk < 32; kk++) {
            int k = j * 32 + kk;
            float4 wu = *(float4*)(WUs + k * D + lane * 4);
            float4 wv = *(float4*)(WVs + k * D + lane * 4);
#pragma unroll
            for (int n = 0; n < 2; n++) {
#pragma unroll
                for (int ax = 0; ax < 3; ax++) {
                    float v = __shfl_sync(0xffffffffu, xr[ax][j][n], kk);
                    aU[ax][n].x += v * wu.x; aU[ax][n].y += v * wu.y;
                    aU[ax][n].z += v * wu.z; aU[ax][n].w += v * wu.w;
                    aV[ax][n].x += v * wv.x; aV[ax][n].y += v * wv.y;
                    aV[ax][n].z += v * wv.z; aV[ax][n].w += v * wv.w;
                }
            }
        }
    }
#pragma unroll
    for (int n = 0; n < 2; n++) {
        int node = n0 + n;
        if (node < NN) {
#pragma unroll
            for (int ax = 0; ax < 3; ax++)
                *(float4*)(g_uv + (size_t)node * 384 + ax * 128 + lane * 4) = aU[ax][n];
            float4 vq, ip;
            vq.x = aV[0][n].x * aV[0][n].x + aV[1][n].x * aV[1][n].x + aV[2][n].x * aV[2][n].x;
            vq.y = aV[0][n].y * aV[0][n].y + aV[1][n].y * aV[1][n].y + aV[2][n].y * aV[2][n].y;
            vq.z = aV[0][n].z * aV[0][n].z + aV[1][n].z * aV[1][n].z + aV[2][n].z * aV[2][n].z;
            vq.w = aV[0][n].w * aV[0][n].w + aV[1][n].w * aV[1][n].w + aV[2][n].w * aV[2][n].w;
            ip.x = aU[0][n].x * aV[0][n].x + aU[1][n].x * aV[1][n].x + aU[2][n].x * aV[2][n].x;
            ip.y = aU[0][n].y * aV[0][n].y + aU[1][n].y * aV[1][n].y + aU[2][n].y * aV[2][n].y;
            ip.z = aU[0][n].z * aV[0][n].z + aU[1][n].z * aV[1][n].z + aU[2][n].z * aV[2][n].z;
            ip.w = aU[0][n].w * aV[0][n].w + aU[1][n].w * aV[1][n].w + aU[2][n].w * aV[2][n].w;
            *(float4*)(g_vvsq + (size_t)node * D + lane * 4) = vq;
            *(float4*)(g_ip + (size_t)node * D + lane * 4) = ip;
        }
    }
}

// ---------------- kernel 6: h2 = silu([s, Vvsq] @ Wa1 + ba1) -----------------
__global__ void __launch_bounds__(512, 1)
k_a1(const float* __restrict__ W, const float* __restrict__ b,
     const float* __restrict__ out) {
    extern __shared__ float sm[];
    float* Ws = sm;                 // 32768
    float* bs = sm + 32768;         // 128
    int tid = threadIdx.x;
    {
        const float4* Wv = (const float4*)W;
        float4* Wsv = (float4*)Ws;
        for (int i = tid; i < 8192; i += 512) Wsv[i] = Wv[i];
        if (tid < 128) bs[tid] = b[tid];
    }
    __syncthreads();
    int warp = tid >> 5, lane = tid & 31;
    int n0 = blockIdx.x * 64 + warp * 4;

    float xr[8][4];
#pragma unroll
    for (int n = 0; n < 4; n++) {
        int node = n0 + n;
        if (node < NN) {
#pragma unroll
            for (int j = 0; j < 4; j++)
                xr[j][n] = out[(size_t)node * D + j * 32 + lane];
#pragma unroll
            for (int j = 0; j < 4; j++)
                xr[4 + j][n] = g_vvsq[(size_t)node * D + j * 32 + lane];
        } else {
#pragma unroll
            for (int j = 0; j < 8; j++) xr[j][n] = 0.f;
        }
    }
    float4 bv = *(float4*)(bs + lane * 4);
    float4 acc[4];
#pragma unroll
    for (int n = 0; n < 4; n++) acc[n] = bv;

#pragma unroll
    for (int j = 0; j < 8; j++) {
#pragma unroll
        for (int kk = 0; kk < 32; kk++) {
            int k = j * 32 + kk;
            float4 w = *(float4*)(Ws + k * D + lane * 4);
#pragma unroll
            for (int n = 0; n < 4; n++) {
                float xv = __shfl_sync(0xffffffffu, xr[j][n], kk);
                acc[n].x += xv * w.x; acc[n].y += xv * w.y;
                acc[n].z += xv * w.z; acc[n].w += xv * w.w;
            }
        }
    }
#pragma unroll
    for (int n = 0; n < 4; n++) {
        int node = n0 + n;
        if (node < NN) {
            float4 o;
            o.x = silu_f(acc[n].x); o.y = silu_f(acc[n].y);
            o.z = silu_f(acc[n].z); o.w = silu_f(acc[n].w);
            *(float4*)(g_h2 + (size_t)node * D + lane * 4) = o;
        }
    }
}

// ---------------- kernel 7: a = h2 @ Wa2 + ba2, final in-place update --------
__global__ void __launch_bounds__(512, 1)
k_a2(const float* __restrict__ W, const float* __restrict__ b,
     float* __restrict__ out) {
    extern __shared__ float sm[];
    float* Ws = sm;                 // 49152
    float* bs = sm + 49152;         // 384
    int tid = threadIdx.x;
    {
        const float4* Wv = (const float4*)W;
        float4* Wsv = (float4*)Ws;
        for (int i = tid; i < 12288; i += 512) Wsv[i] = Wv[i];
        if (tid < 384) bs[tid] = b[tid];
    }
    __syncthreads();
    int warp = tid >> 5, lane = tid & 31;
    int n0 = blockIdx.x * 64 + warp * 4;
    float* out_s = out;
    float* out_v = out + (size_t)NN * D;

    float xr[4][4];
#pragma unroll
    for (int n = 0; n < 4; n++) {
        int node = n0 + n;
#pragma unroll
        for (int j = 0; j < 4; j++)
            xr[j][n] = (node < NN) ? g_h2[(size_t)node * D + j * 32 + lane] : 0.f;
    }
    float4 b0 = *(float4*)(bs + lane * 4);
    float4 b1 = *(float4*)(bs + 128 + lane * 4);
    float4 b2 = *(float4*)(bs + 256 + lane * 4);
    float4 a0[4], a1[4], a2[4];
#pragma unroll
    for (int n = 0; n < 4; n++) { a0[n] = b0; a1[n] = b1; a2[n] = b2; }

#pragma unroll
    for (int j = 0; j < 4; j++) {
#pragma unroll
        for (int kk = 0; kk < 32; kk++) {
            int k = j * 32 + kk;
            float4 w0 = *(float4*)(Ws + k * 384 + lane * 4);
            float4 w1 = *(float4*)(Ws + k * 384 + 128 + lane * 4);
            float4 w2 = *(float4*)(Ws + k * 384 + 256 + lane * 4);
#pragma unroll
            for (int n = 0; n < 4; n++) {
                float xv = __shfl_sync(0xffffffffu, xr[j][n], kk);
                a0[n].x += xv * w0.x; a0[n].y += xv * w0.y; a0[n].z += xv * w0.z; a0[n].w += xv * w0.w;
                a1[n].x += xv * w1.x; a1[n].y += xv * w1.y; a1[n].z += xv * w1.z; a1[n].w += xv * w1.w;
                a2[n].x += xv * w2.x; a2[n].y += xv * w2.y; a2[n].z += xv * w2.z; a2[n].w += xv * w2.w;
            }
        }
    }
#pragma unroll
    for (int n = 0; n < 4; n++) {
        int node = n0 + n;
        if (node < NN) {
            float* sp = out_s + (size_t)node * D + lane * 4;
            float4 s = *(float4*)sp;
            float4 ip = *(float4*)(g_ip + (size_t)node * D + lane * 4);
            s.x += a0[n].x + a1[n].x * ip.x;
            s.y += a0[n].y + a1[n].y * ip.y;
            s.z += a0[n].z + a1[n].z * ip.z;
            s.w += a0[n].w + a1[n].w * ip.w;
            *(float4*)sp = s;
            const float* uvb = g_uv + (size_t)node * 384 + lane * 4;
            float* ovb = out_v + (size_t)node * 384 + lane * 4;
#pragma unroll
            for (int ax = 0; ax < 3; ax++) {
                float4 uv = *(const float4*)(uvb + ax * 128);
                float4 vv = *(float4*)(ovb + ax * 128);
                vv.x += a2[n].x * uv.x;
                vv.y += a2[n].y * uv.y;
                vv.z += a2[n].z * uv.z;
                vv.w += a2[n].w * uv.w;
                *(float4*)(ovb + ax * 128) = vv;
            }
        }
    }
}

// ---------------- launch ------------------------------------------------------
extern "C" void kernel_launch(void* const* d_in, const int* in_sizes, int n_in,
                              void* d_out, int out_size) {
    const float* ns  = (const float*)d_in[0];
    const float* nv  = (const float*)d_in[1];
    const float* es  = (const float*)d_in[2];
    const float* ev  = (const float*)d_in[3];
    const float* en  = (const float*)d_in[4];
    const int*   ei  = (const int*)d_in[5];
    const float* Wf  = (const float*)d_in[6];
    const float* bf  = (const float*)d_in[7];
    const float* Wm1 = (const float*)d_in[8];
    const float* bm1 = (const float*)d_in[9];
    const float* Wm2 = (const float*)d_in[10];
    const float* bm2 = (const float*)d_in[11];
    const float* WU  = (const float*)d_in[12];
    const float* WV  = (const float*)d_in[13];
    const float* Wa1 = (const float*)d_in[14];
    const float* ba1 = (const float*)d_in[15];
    const float* Wa2 = (const float*)d_in[16];
    const float* ba2 = (const float*)d_in[17];
    float* out = (float*)d_out;

    const int SM_MLP1 = (16384 + 128) * 4;
    const int SM_GEMM = (49152 + 384) * 4;        // mlp2 / a2
    const int SM_UV   = 32768 * 4;
    const int SM_A1   = (32768 + 128) * 4;

    cudaFuncSetAttribute(k_mlp1, cudaFuncAttributeMaxDynamicSharedMemorySize, SM_MLP1);
    cudaFuncSetAttribute(k_mlp2, cudaFuncAttributeMaxDynamicSharedMemorySize, SM_GEMM);
    cudaFuncSetAttribute(k_uv,   cudaFuncAttributeMaxDynamicSharedMemorySize, SM_UV);
    cudaFuncSetAttribute(k_a1,   cudaFuncAttributeMaxDynamicSharedMemorySize, SM_A1);
    cudaFuncSetAttribute(k_a2,   cudaFuncAttributeMaxDynamicSharedMemorySize, SM_GEMM);

    int gnode = (NN + 63) / 64;   // 313
    int guv   = (NN + 31) / 32;   // 625

    k_init<<<2048, 256>>>(ns, nv, out);
    k_mlp1<<<gnode, 512, SM_MLP1>>>(ns, Wm1, bm1);
    k_mlp2<<<gnode, 512, SM_GEMM>>>(Wm2, bm2);
    k_edge<<<148, 384>>>(es, ev, en, ei, Wf, bf, nv, out);
    k_uv<<<guv, 512, SM_UV>>>(WU, WV, out);
    k_a1<<<gnode, 512, SM_A1>>>(Wa1, ba1, out);
    k_a2<<<gnode, 512, SM_GEMM>>>(Wa2, ba2, out);
}

// round 11
// speedup vs baseline: 1.4509x; 1.0731x over previous
#include <cuda_runtime.h>

#define D      128
#define NN     20000
#define NE     600000
#define ESZ    20

typedef unsigned long long u64;

// ---------------- scratch (device globals; no allocations allowed) ----------
__device__ float g_h1[NN * D];
__device__ float g_so[NN * 3 * D];
__device__ float g_uv[NN * 3 * D];
__device__ float g_vvsq[NN * D];
__device__ float g_ip[NN * D];
__device__ float g_h2[NN * D];

__device__ __forceinline__ float silu_f(float x) {
    return x / (1.0f + __expf(-x));
}
__device__ __forceinline__ u64 pk2(float lo, float hi) {
    u64 r; asm("mov.b64 %0,{%1,%2};" : "=l"(r) : "f"(lo), "f"(hi)); return r;
}
__device__ __forceinline__ void upk2(u64 v, float& lo, float& hi) {
    asm("mov.b64 {%0,%1},%2;" : "=f"(lo), "=f"(hi) : "l"(v));
}
__device__ __forceinline__ u64 fma2(u64 a, u64 b, u64 c) {
    u64 d; asm("fma.rn.f32x2 %0,%1,%2,%3;" : "=l"(d) : "l"(a), "l"(b), "l"(c)); return d;
}
__device__ __forceinline__ u64 mul2(u64 a, u64 b) {
    u64 d; asm("mul.rn.f32x2 %0,%1,%2;" : "=l"(d) : "l"(a), "l"(b)); return d;
}
__device__ __forceinline__ void red4(float* p, float a, float b, float c, float d) {
    asm volatile("red.global.add.v4.f32 [%0], {%1,%2,%3,%4};"
                 :: "l"(p), "f"(a), "f"(b), "f"(c), "f"(d) : "memory");
}
__device__ __forceinline__ void red2(float* p, float a, float b) {
    asm volatile("red.global.add.v2.f32 [%0], {%1,%2};"
                 :: "l"(p), "f"(a), "f"(b) : "memory");
}

// ---------------- kernel 1: init output with residuals -----------------------
__global__ void k_init(const float* __restrict__ ns, const float* __restrict__ nv,
                       float* __restrict__ out) {
    const float4* a = (const float4*)ns;
    const float4* b = (const float4*)nv;
    float4* os = (float4*)out;
    float4* ov = os + (NN * D) / 4;
    const int ts = NN * D / 4;
    const int tv = NN * 3 * D / 4;
    for (int i = blockIdx.x * blockDim.x + threadIdx.x; i < ts; i += gridDim.x * blockDim.x)
        os[i] = a[i];
    for (int i = blockIdx.x * blockDim.x + threadIdx.x; i < tv; i += gridDim.x * blockDim.x)
        ov[i] = b[i];
}

// ---------------- kernel 2: h1 = silu(ns @ Wm1 + bm1) ------------------------
__global__ void __launch_bounds__(512, 1)
k_mlp1(const float* __restrict__ x, const float* __restrict__ W,
       const float* __restrict__ b) {
    extern __shared__ float sm[];
    float* Ws = sm;
    float* bs = sm + 16384;
    int tid = threadIdx.x;
    {
        const float4* Wv = (const float4*)W;
        float4* Wsv = (float4*)Ws;
        for (int i = tid; i < 4096; i += 512) Wsv[i] = Wv[i];
        if (tid < 128) bs[tid] = b[tid];
    }
    __syncthreads();
    int warp = tid >> 5, lane = tid & 31;
    int n0 = blockIdx.x * 64 + warp * 4;

    float xr[4][4];
#pragma unroll
    for (int n = 0; n < 4; n++) {
        int node = n0 + n;
#pragma unroll
        for (int j = 0; j < 4; j++)
            xr[j][n] = (node < NN) ? x[(size_t)node * D + j * 32 + lane] : 0.f;
    }
    ulonglong2 bv = *(const ulonglong2*)(bs + lane * 4);
    u64 al[4], ah[4];
#pragma unroll
    for (int n = 0; n < 4; n++) { al[n] = bv.x; ah[n] = bv.y; }

#pragma unroll
    for (int j = 0; j < 4; j++) {
#pragma unroll
        for (int kk = 0; kk < 32; kk++) {
            int k = j * 32 + kk;
            ulonglong2 w = *(const ulonglong2*)(Ws + k * D + lane * 4);
#pragma unroll
            for (int n = 0; n < 4; n++) {
                float v = __shfl_sync(0xffffffffu, xr[j][n], kk);
                u64 v2 = pk2(v, v);
                al[n] = fma2(v2, w.x, al[n]);
                ah[n] = fma2(v2, w.y, ah[n]);
            }
        }
    }
#pragma unroll
    for (int n = 0; n < 4; n++) {
        int node = n0 + n;
        if (node < NN) {
            float x0, x1, x2, x3;
            upk2(al[n], x0, x1); upk2(ah[n], x2, x3);
            float4 o;
            o.x = silu_f(x0); o.y = silu_f(x1);
            o.z = silu_f(x2); o.w = silu_f(x3);
            *(float4*)(g_h1 + (size_t)node * D + lane * 4) = o;
        }
    }
}

// ---------------- kernel 3: scalar_output = h1 @ Wm2 + bm2  (packed) ---------
__global__ void __launch_bounds__(512, 1)
k_mlp2(const float* __restrict__ W, const float* __restrict__ b) {
    extern __shared__ float sm[];
    float* Ws = sm;                 // 49152
    float* bs = sm + 49152;         // 384
    int tid = threadIdx.x;
    {
        const float4* Wv = (const float4*)W;
        float4* Wsv = (float4*)Ws;
        for (int i = tid; i < 12288; i += 512) Wsv[i] = Wv[i];
        if (tid < 384) bs[tid] = b[tid];
    }
    __syncthreads();
    int warp = tid >> 5, lane = tid & 31;
    int n0 = blockIdx.x * 64 + warp * 4;

    float xr[4][4];
#pragma unroll
    for (int n = 0; n < 4; n++) {
        int node = n0 + n;
#pragma unroll
        for (int j = 0; j < 4; j++)
            xr[j][n] = (node < NN) ? g_h1[(size_t)node * D + j * 32 + lane] : 0.f;
    }
    ulonglong2 b0 = *(const ulonglong2*)(bs + lane * 4);
    ulonglong2 b1 = *(const ulonglong2*)(bs + 128 + lane * 4);
    ulonglong2 b2 = *(const ulonglong2*)(bs + 256 + lane * 4);
    u64 a0l[4], a0h[4], a1l[4], a1h[4], a2l[4], a2h[4];
#pragma unroll
    for (int n = 0; n < 4; n++) {
        a0l[n] = b0.x; a0h[n] = b0.y;
        a1l[n] = b1.x; a1h[n] = b1.y;
        a2l[n] = b2.x; a2h[n] = b2.y;
    }

#pragma unroll
    for (int j = 0; j < 4; j++) {
#pragma unroll
        for (int kk = 0; kk < 32; kk++) {
            int k = j * 32 + kk;
            const float* wp = Ws + k * 384 + lane * 4;
            ulonglong2 w0 = *(const ulonglong2*)wp;
            ulonglong2 w1 = *(const ulonglong2*)(wp + 128);
            ulonglong2 w2 = *(const ulonglong2*)(wp + 256);
#pragma unroll
            for (int n = 0; n < 4; n++) {
                float xv = __shfl_sync(0xffffffffu, xr[j][n], kk);
                u64 xv2 = pk2(xv, xv);
                a0l[n] = fma2(xv2, w0.x, a0l[n]); a0h[n] = fma2(xv2, w0.y, a0h[n]);
                a1l[n] = fma2(xv2, w1.x, a1l[n]); a1h[n] = fma2(xv2, w1.y, a1h[n]);
                a2l[n] = fma2(xv2, w2.x, a2l[n]); a2h[n] = fma2(xv2, w2.y, a2h[n]);
            }
        }
    }
#pragma unroll
    for (int n = 0; n < 4; n++) {
        int node = n0 + n;
        if (node < NN) {
            float* o = g_so + (size_t)node * 384 + lane * 4;
            *(ulonglong2*)o         = make_ulonglong2(a0l[n], a0h[n]);
            *(ulonglong2*)(o + 128) = make_ulonglong2(a1l[n], a1h[n]);
            *(ulonglong2*)(o + 256) = make_ulonglong2(a2l[n], a2h[n]);
        }
    }
}

// ---------------- kernel 4: fused edge filter + gather + scatter (packed) ----
// 3 independent warps per edge; 480 threads (15 warps = 5 trios).
__global__ void __launch_bounds__(480, 1)
k_edge(const float* __restrict__ es, const float* __restrict__ ev,
       const float* __restrict__ en, const int* __restrict__ ei,
       const float* __restrict__ Wf, const float* __restrict__ bf,
       const float* __restrict__ nv, float* __restrict__ out) {
    int gwarp = (blockIdx.x * blockDim.x + threadIdx.x) >> 5;
    int lane = threadIdx.x & 31;
    int trio = gwarp / 3, role = gwarp % 3;
    const int step = (gridDim.x * 480 / 32) / 3;   // 740
    if (trio >= NE) return;

    float* out_s = out;
    float* out_v = out + (size_t)NN * D;

    if (role == 2) {
        // ---------- scalar path: cols 256..383, 2 packed pairs/lane ----------
        u64 W0[ESZ], W1[ESZ];
        {
            const float* wb = Wf + 256 + lane * 4;
#pragma unroll
            for (int k = 0; k < ESZ; k++) {
                ulonglong2 w = *(const ulonglong2*)(wb + k * 384);
                W0[k] = w.x; W1[k] = w.y;
            }
        }
        ulonglong2 bfr = *(const ulonglong2*)(bf + 256 + lane * 4);

        int e = trio;
        float esvA = (lane < ESZ) ? __ldg(es + (size_t)e * ESZ + lane) : 0.f;
        int2 sdA = __ldg((const int2*)ei + e);
        float rA = __ldg(en + e);

        int e1 = e + step;
        bool hasB = e1 < NE;
        float esvB = 0.f; int2 sdB = {0, 0}; float rB = 9.f;
        if (hasB) {
            esvB = (lane < ESZ) ? __ldg(es + (size_t)e1 * ESZ + lane) : 0.f;
            sdB = __ldg((const int2*)ei + e1);
            rB = __ldg(en + e1);
        }
        ulonglong2 soA = *(const ulonglong2*)(g_so + (size_t)sdA.x * 384 + 256 + lane * 4);

        while (true) {
            int e2 = e1 + step;
            float esvC = 0.f; int2 sdC = {0, 0}; float rC = 9.f;
            if (e2 < NE) {
                esvC = (lane < ESZ) ? __ldg(es + (size_t)e2 * ESZ + lane) : 0.f;
                sdC = __ldg((const int2*)ei + e2);
                rC = __ldg(en + e2);
            }
            ulonglong2 soB = make_ulonglong2(0, 0);
            if (hasB)
                soB = *(const ulonglong2*)(g_so + (size_t)sdB.x * 384 + 256 + lane * 4);

            float fc = (rA < 5.0f) ? 0.5f * (cospif(rA * 0.2f) + 1.0f) : 0.0f;
            u64 fc2 = pk2(fc, fc);
            u64 f0 = bfr.x, f1 = bfr.y;
#pragma unroll
            for (int k = 0; k < ESZ; k++) {
                float ek = __shfl_sync(0xffffffffu, esvA, k);
                u64 ek2 = pk2(ek, ek);
                f0 = fma2(ek2, W0[k], f0);
                f1 = fma2(ek2, W1[k], f1);
            }
            u64 m0 = mul2(mul2(f0, fc2), soA.x);
            u64 m1 = mul2(mul2(f1, fc2), soA.y);
            float x0, y0, x1, y1;
            upk2(m0, x0, y0); upk2(m1, x1, y1);
            red4(out_s + (size_t)sdA.y * D + lane * 4, x0, y0, x1, y1);

            if (!hasB) break;
            e = e1; e1 = e2;
            esvA = esvB; sdA = sdB; rA = rB; soA = soB;
            esvB = esvC; sdB = sdC; rB = rC;
            hasB = e1 < NE;
        }
    } else {
        // ---------- vector-half path: channels ch..ch+1 (one packed pair) ----
        int ch = role * 64 + lane * 2;
        u64 WN2[ESZ], WE2[ESZ];
#pragma unroll
        for (int k = 0; k < ESZ; k++) {
            WN2[k] = *(const u64*)(Wf + k * 384 + ch);
            WE2[k] = *(const u64*)(Wf + k * 384 + 128 + ch);
        }
        u64 bN2 = *(const u64*)(bf + ch);
        u64 bE2 = *(const u64*)(bf + 128 + ch);

        int e = trio;
        float esvA = (lane < ESZ) ? __ldg(es + (size_t)e * ESZ + lane) : 0.f;
        int2 sdA = __ldg((const int2*)ei + e);
        float rA = __ldg(en + e);

        int e1 = e + step;
        bool hasB = e1 < NE;
        float esvB = 0.f; int2 sdB = {0, 0}; float rB = 9.f;
        if (hasB) {
            esvB = (lane < ESZ) ? __ldg(es + (size_t)e1 * ESZ + lane) : 0.f;
            sdB = __ldg((const int2*)ei + e1);
            rB = __ldg(en + e1);
        }
        u64 soNA = *(const u64*)(g_so + (size_t)sdA.x * 384 + ch);
        u64 soEA = *(const u64*)(g_so + (size_t)sdA.x * 384 + 128 + ch);
        const float* nvbA = nv + (size_t)sdA.x * 384 + ch;
        u64 nA0 = *(const u64*)nvbA;
        u64 nA1 = *(const u64*)(nvbA + 128);
        u64 nA2 = *(const u64*)(nvbA + 256);
        float evA0 = __ldg(ev + 3 * (size_t)e);
        float evA1 = __ldg(ev + 3 * (size_t)e + 1);
        float evA2 = __ldg(ev + 3 * (size_t)e + 2);

        while (true) {
            int e2 = e1 + step;
            float esvC = 0.f; int2 sdC = {0, 0}; float rC = 9.f;
            if (e2 < NE) {
                esvC = (lane < ESZ) ? __ldg(es + (size_t)e2 * ESZ + lane) : 0.f;
                sdC = __ldg((const int2*)ei + e2);
                rC = __ldg(en + e2);
            }
            u64 soNB = 0, soEB = 0, nB0 = 0, nB1 = 0, nB2 = 0;
            float evB0 = 0.f, evB1 = 0.f, evB2 = 0.f;
            if (hasB) {
                soNB = *(const u64*)(g_so + (size_t)sdB.x * 384 + ch);
                soEB = *(const u64*)(g_so + (size_t)sdB.x * 384 + 128 + ch);
                const float* nvbB = nv + (size_t)sdB.x * 384 + ch;
                nB0 = *(const u64*)nvbB;
                nB1 = *(const u64*)(nvbB + 128);
                nB2 = *(const u64*)(nvbB + 256);
                evB0 = __ldg(ev + 3 * (size_t)e1);
                evB1 = __ldg(ev + 3 * (size_t)e1 + 1);
                evB2 = __ldg(ev + 3 * (size_t)e1 + 2);
            }
            float fc = (rA < 5.0f) ? 0.5f * (cospif(rA * 0.2f) + 1.0f) : 0.0f;
            u64 fc2 = pk2(fc, fc);
            u64 fN = bN2, fE = bE2;
#pragma unroll
            for (int k = 0; k < ESZ; k++) {
                float ek = __shfl_sync(0xffffffffu, esvA, k);
                u64 ek2 = pk2(ek, ek);
                fN = fma2(ek2, WN2[k], fN);
                fE = fma2(ek2, WE2[k], fE);
            }
            u64 gn = mul2(mul2(fN, fc2), soNA);
            u64 ge = mul2(mul2(fE, fc2), soEA);
            u64 m0 = fma2(gn, nA0, mul2(ge, pk2(evA0, evA0)));
            u64 m1 = fma2(gn, nA1, mul2(ge, pk2(evA1, evA1)));
            u64 m2 = fma2(gn, nA2, mul2(ge, pk2(evA2, evA2)));
            float* ovb = out_v + (size_t)sdA.y * 384 + ch;
            float l, h;
            upk2(m0, l, h); red2(ovb, l, h);
            upk2(m1, l, h); red2(ovb + 128, l, h);
            upk2(m2, l, h); red2(ovb + 256, l, h);

            if (!hasB) break;
            e = e1; e1 = e2;
            esvA = esvB; sdA = sdB; rA = rB;
            soNA = soNB; soEA = soEB;
            nA0 = nB0; nA1 = nB1; nA2 = nB2;
            evA0 = evB0; evA1 = evB1; evA2 = evB2;
            esvB = esvC; sdB = sdC; rB = rC;
            hasB = e1 < NE;
        }
    }
}

// ---------------- kernel 5: Uv, |Vv|^2, <Uv,Vv>  (packed) --------------------
__global__ void __launch_bounds__(512, 1)
k_uv(const float* __restrict__ WU, const float* __restrict__ WV,
     const float* __restrict__ out) {
    extern __shared__ float sm[];
    float* WUs = sm;
    float* WVs = sm + 16384;
    const float* v_in = out + (size_t)NN * D;
    int tid = threadIdx.x;
    {
        const float4* u4 = (const float4*)WU;
        const float4* v4 = (const float4*)WV;
        float4* su = (float4*)WUs;
        float4* sv = (float4*)WVs;
        for (int i = tid; i < 4096; i += 512) { su[i] = u4[i]; sv[i] = v4[i]; }
    }
    __syncthreads();
    int warp = tid >> 5, lane = tid & 31;
    int n0 = blockIdx.x * 32 + warp * 2;

    float xr[3][4][2];
#pragma unroll
    for (int n = 0; n < 2; n++) {
        int node = n0 + n;
#pragma unroll
        for (int ax = 0; ax < 3; ax++)
#pragma unroll
            for (int j = 0; j < 4; j++)
                xr[ax][j][n] = (node < NN)
                    ? v_in[(size_t)node * 384 + ax * 128 + j * 32 + lane] : 0.f;
    }
    u64 aUl[3][2], aUh[3][2], aVl[3][2], aVh[3][2];
#pragma unroll
    for (int ax = 0; ax < 3; ax++)
#pragma unroll
        for (int n = 0; n < 2; n++) {
            aUl[ax][n] = 0; aUh[ax][n] = 0;
            aVl[ax][n] = 0; aVh[ax][n] = 0;
        }

#pragma unroll
    for (int j = 0; j < 4; j++) {
#pragma unroll
        for (int kk = 0; kk < 32; kk++) {
            int k = j * 32 + kk;
            ulonglong2 wu = *(const ulonglong2*)(WUs + k * D + lane * 4);
            ulonglong2 wv = *(const ulonglong2*)(WVs + k * D + lane * 4);
#pragma unroll
            for (int n = 0; n < 2; n++) {
#pragma unroll
                for (int ax = 0; ax < 3; ax++) {
                    float v = __shfl_sync(0xffffffffu, xr[ax][j][n], kk);
                    u64 v2 = pk2(v, v);
                    aUl[ax][n] = fma2(v2, wu.x, aUl[ax][n]);
                    aUh[ax][n] = fma2(v2, wu.y, aUh[ax][n]);
                    aVl[ax][n] = fma2(v2, wv.x, aVl[ax][n]);
                    aVh[ax][n] = fma2(v2, wv.y, aVh[ax][n]);
                }
            }
        }
    }
#pragma unroll
    for (int n = 0; n < 2; n++) {
        int node = n0 + n;
        if (node < NN) {
            float u[3][4], vv[3][4];
#pragma unroll
            for (int ax = 0; ax < 3; ax++) {
                *(ulonglong2*)(g_uv + (size_t)node * 384 + ax * 128 + lane * 4)
                    = make_ulonglong2(aUl[ax][n], aUh[ax][n]);
                upk2(aUl[ax][n], u[ax][0], u[ax][1]);
                upk2(aUh[ax][n], u[ax][2], u[ax][3]);
                upk2(aVl[ax][n], vv[ax][0], vv[ax][1]);
                upk2(aVh[ax][n], vv[ax][2], vv[ax][3]);
            }
            float4 vq, ip;
            float* vqp = (float*)&vq;
            float* ipp = (float*)&ip;
#pragma unroll
            for (int c = 0; c < 4; c++) {
                vqp[c] = vv[0][c] * vv[0][c] + vv[1][c] * vv[1][c] + vv[2][c] * vv[2][c];
                ipp[c] = u[0][c] * vv[0][c] + u[1][c] * vv[1][c] + u[2][c] * vv[2][c];
            }
            *(float4*)(g_vvsq + (size_t)node * D + lane * 4) = vq;
            *(float4*)(g_ip + (size_t)node * D + lane * 4) = ip;
        }
    }
}

// ---------------- kernel 6: h2 = silu([s, Vvsq] @ Wa1 + ba1)  (packed) -------
__global__ void __launch_bounds__(512, 1)
k_a1(const float* __restrict__ W, const float* __restrict__ b,
     const float* __restrict__ out) {
    extern __shared__ float sm[];
    float* Ws = sm;                 // 32768
    float* bs = sm + 32768;         // 128
    int tid = threadIdx.x;
    {
        const float4* Wv = (const float4*)W;
        float4* Wsv = (float4*)Ws;
        for (int i = tid; i < 8192; i += 512) Wsv[i] = Wv[i];
        if (tid < 128) bs[tid] = b[tid];
    }
    __syncthreads();
    int warp = tid >> 5, lane = tid & 31;
    int n0 = blockIdx.x * 64 + warp * 4;

    float xr[8][4];
#pragma unroll
    for (int n = 0; n < 4; n++) {
        int node = n0 + n;
        if (node < NN) {
#pragma unroll
            for (int j = 0; j < 4; j++)
                xr[j][n] = out[(size_t)node * D + j * 32 + lane];
#pragma unroll
            for (int j = 0; j < 4; j++)
                xr[4 + j][n] = g_vvsq[(size_t)node * D + j * 32 + lane];
        } else {
#pragma unroll
            for (int j = 0; j < 8; j++) xr[j][n] = 0.f;
        }
    }
    ulonglong2 bv = *(const ulonglong2*)(bs + lane * 4);
    u64 al[4], ah[4];
#pragma unroll
    for (int n = 0; n < 4; n++) { al[n] = bv.x; ah[n] = bv.y; }

#pragma unroll
    for (int j = 0; j < 8; j++) {
#pragma unroll
        for (int kk = 0; kk < 32; kk++) {
            int k = j * 32 + kk;
            ulonglong2 w = *(const ulonglong2*)(Ws + k * D + lane * 4);
#pragma unroll
            for (int n = 0; n < 4; n++) {
                float xv = __shfl_sync(0xffffffffu, xr[j][n], kk);
                u64 xv2 = pk2(xv, xv);
                al[n] = fma2(xv2, w.x, al[n]);
                ah[n] = fma2(xv2, w.y, ah[n]);
            }
        }
    }
#pragma unroll
    for (int n = 0; n < 4; n++) {
        int node = n0 + n;
        if (node < NN) {
            float x0, x1, x2, x3;
            upk2(al[n], x0, x1); upk2(ah[n], x2, x3);
            float4 o;
            o.x = silu_f(x0); o.y = silu_f(x1);
            o.z = silu_f(x2); o.w = silu_f(x3);
            *(float4*)(g_h2 + (size_t)node * D + lane * 4) = o;
        }
    }
}

// ---------------- kernel 7: a = h2 @ Wa2 + ba2, final update  (packed) -------
__global__ void __launch_bounds__(512, 1)
k_a2(const float* __restrict__ W, const float* __restrict__ b,
     float* __restrict__ out) {
    extern __shared__ float sm[];
    float* Ws = sm;                 // 49152
    float* bs = sm + 49152;         // 384
    int tid = threadIdx.x;
    {
        const float4* Wv = (const float4*)W;
        float4* Wsv = (float4*)Ws;
        for (int i = tid; i < 12288; i += 512) Wsv[i] = Wv[i];
        if (tid < 384) bs[tid] = b[tid];
    }
    __syncthreads();
    int warp = tid >> 5, lane = tid & 31;
    int n0 = blockIdx.x * 64 + warp * 4;
    float* out_s = out;
    float* out_v = out + (size_t)NN * D;

    float xr[4][4];
#pragma unroll
    for (int n = 0; n < 4; n++) {
        int node = n0 + n;
#pragma unroll
        for (int j = 0; j < 4; j++)
            xr[j][n] = (node < NN) ? g_h2[(size_t)node * D + j * 32 + lane] : 0.f;
    }
    ulonglong2 b0 = *(const ulonglong2*)(bs + lane * 4);
    ulonglong2 b1 = *(const ulonglong2*)(bs + 128 + lane * 4);
    ulonglong2 b2 = *(const ulonglong2*)(bs + 256 + lane * 4);
    u64 a0l[4], a0h[4], a1l[4], a1h[4], a2l[4], a2h[4];
#pragma unroll
    for (int n = 0; n < 4; n++) {
        a0l[n] = b0.x; a0h[n] = b0.y;
        a1l[n] = b1.x; a1h[n] = b1.y;
        a2l[n] = b2.x; a2h[n] = b2.y;
    }

#pragma unroll
    for (int j = 0; j < 4; j++) {
#pragma unroll
        for (int kk = 0; kk < 32; kk++) {
            int k = j * 32 + kk;
            const float* wp = Ws + k * 384 + lane * 4;
            ulonglong2 w0 = *(const ulonglong2*)wp;
            ulonglong2 w1 = *(const ulonglong2*)(wp + 128);
            ulonglong2 w2 = *(const ulonglong2*)(wp + 256);
#pragma unroll
            for (int n = 0; n < 4; n++) {
                float xv = __shfl_sync(0xffffffffu, xr[j][n], kk);
                u64 xv2 = pk2(xv, xv);
                a0l[n] = fma2(xv2, w0.x, a0l[n]); a0h[n] = fma2(xv2, w0.y, a0h[n]);
                a1l[n] = fma2(xv2, w1.x, a1l[n]); a1h[n] = fma2(xv2, w1.y, a1h[n]);
                a2l[n] = fma2(xv2, w2.x, a2l[n]); a2h[n] = fma2(xv2, w2.y, a2h[n]);
            }
        }
    }
#pragma unroll
    for (int n = 0; n < 4; n++) {
        int node = n0 + n;
        if (node < NN) {
            float A0[4], A1[4], A2[4];
            upk2(a0l[n], A0[0], A0[1]); upk2(a0h[n], A0[2], A0[3]);
            upk2(a1l[n], A1[0], A1[1]); upk2(a1h[n], A1[2], A1[3]);
            upk2(a2l[n], A2[0], A2[1]); upk2(a2h[n], A2[2], A2[3]);
            float* sp = out_s + (size_t)node * D + lane * 4;
            float4 s = *(float4*)sp;
            float4 ip = *(float4*)(g_ip + (size_t)node * D + lane * 4);
            s.x += A0[0] + A1[0] * ip.x;
            s.y += A0[1] + A1[1] * ip.y;
            s.z += A0[2] + A1[2] * ip.z;
            s.w += A0[3] + A1[3] * ip.w;
            *(float4*)sp = s;
            const float* uvb = g_uv + (size_t)node * 384 + lane * 4;
            float* ovb = out_v + (size_t)node * 384 + lane * 4;
#pragma unroll
            for (int ax = 0; ax < 3; ax++) {
                float4 uv = *(const float4*)(uvb + ax * 128);
                float4 vv = *(float4*)(ovb + ax * 128);
                vv.x += A2[0] * uv.x;
                vv.y += A2[1] * uv.y;
                vv.z += A2[2] * uv.z;
                vv.w += A2[3] * uv.w;
                *(float4*)(ovb + ax * 128) = vv;
            }
        }
    }
}

// ---------------- launch ------------------------------------------------------
extern "C" void kernel_launch(void* const* d_in, const int* in_sizes, int n_in,
                              void* d_out, int out_size) {
    const float* ns  = (const float*)d_in[0];
    const float* nv  = (const float*)d_in[1];
    const float* es  = (const float*)d_in[2];
    const float* ev  = (const float*)d_in[3];
    const float* en  = (const float*)d_in[4];
    const int*   ei  = (const int*)d_in[5];
    const float* Wf  = (const float*)d_in[6];
    const float* bf  = (const float*)d_in[7];
    const float* Wm1 = (const float*)d_in[8];
    const float* bm1 = (const float*)d_in[9];
    const float* Wm2 = (const float*)d_in[10];
    const float* bm2 = (const float*)d_in[11];
    const float* WU  = (const float*)d_in[12];
    const float* WV  = (const float*)d_in[13];
    const float* Wa1 = (const float*)d_in[14];
    const float* ba1 = (const float*)d_in[15];
    const float* Wa2 = (const float*)d_in[16];
    const float* ba2 = (const float*)d_in[17];
    float* out = (float*)d_out;

    const int SM_MLP1 = (16384 + 128) * 4;
    const int SM_GEMM = (49152 + 384) * 4;
    const int SM_UV   = 32768 * 4;
    const int SM_A1   = (32768 + 128) * 4;

    cudaFuncSetAttribute(k_mlp1, cudaFuncAttributeMaxDynamicSharedMemorySize, SM_MLP1);
    cudaFuncSetAttribute(k_mlp2, cudaFuncAttributeMaxDynamicSharedMemorySize, SM_GEMM);
    cudaFuncSetAttribute(k_uv,   cudaFuncAttributeMaxDynamicSharedMemorySize, SM_UV);
    cudaFuncSetAttribute(k_a1,   cudaFuncAttributeMaxDynamicSharedMemorySize, SM_A1);
    cudaFuncSetAttribute(k_a2,   cudaFuncAttributeMaxDynamicSharedMemorySize, SM_GEMM);

    int gnode = (NN + 63) / 64;   // 313
    int guv   = (NN + 31) / 32;   // 625

    k_init<<<2048, 256>>>(ns, nv, out);
    k_mlp1<<<gnode, 512, SM_MLP1>>>(ns, Wm1, bm1);
    k_mlp2<<<gnode, 512, SM_GEMM>>>(Wm2, bm2);
    k_edge<<<148, 480>>>(es, ev, en, ei, Wf, bf, nv, out);
    k_uv<<<guv, 512, SM_UV>>>(WU, WV, out);
    k_a1<<<gnode, 512, SM_A1>>>(Wa1, ba1, out);
    k_a2<<<gnode, 512, SM_GEMM>>>(Wa2, ba2, out);
}